// round 1
// baseline (speedup 1.0000x reference)
#include <cuda_runtime.h>
#include <math.h>

#define MAX_N 100000
#define F 128

// ---------------- scratch (static device globals; no allocation allowed) ----
__device__ float g_deg[MAX_N];
__device__ float g_dinv[MAX_N];
__device__ float g_xw[MAX_N * F];     // x @ W1
__device__ float g_hw[MAX_N];         // h @ W2
__device__ float g_out2[MAX_N];       // layer-2 accumulator

// ---------------- degree / normalization ------------------------------------
__global__ void k_init_deg(float* deg, int N) {
    int i = blockIdx.x * blockDim.x + threadIdx.x;
    if (i < N) deg[i] = 1.0f;  // self-loop weight
}

__global__ void k_deg_accum(const int* __restrict__ col, const float* __restrict__ ew,
                            float* deg, int E) {
    int e = blockIdx.x * blockDim.x + threadIdx.x;
    if (e < E) atomicAdd(&deg[col[e]], ew[e]);
}

__global__ void k_dinv(const float* __restrict__ deg, float* dinv, int N) {
    int i = blockIdx.x * blockDim.x + threadIdx.x;
    if (i < N) {
        float d = deg[i];
        dinv[i] = (d > 0.0f) ? rsqrtf(d) : 0.0f;
    }
}

// ---------------- SGEMM: Y[N,128] = X[N,128] @ W[128,128] -------------------
// 128x128 block tile, 256 threads, 8x8 micro-tile, k-chunk 16.
__global__ void k_gemm128(const float* __restrict__ X, const float* __restrict__ W,
                          float* __restrict__ Y, int N) {
    __shared__ float Xs[16][128];   // [k][row]
    __shared__ float Ws[16][128];   // [k][col]
    int tid  = threadIdx.x;
    int row0 = blockIdx.x * 128;
    int tr = (tid / 16) * 8;        // row offset within tile
    int tc = (tid % 16) * 8;        // col offset within tile

    float acc[8][8];
#pragma unroll
    for (int i = 0; i < 8; i++)
#pragma unroll
        for (int j = 0; j < 8; j++) acc[i][j] = 0.0f;

    for (int k0 = 0; k0 < 128; k0 += 16) {
        // load X chunk transposed: 128 rows x 16 k = 512 float4
#pragma unroll
        for (int it = 0; it < 2; it++) {
            int i = tid + it * 256;
            int r  = i >> 2;
            int kk = (i & 3) * 4;
            int row = row0 + r;
            float4 v = make_float4(0.f, 0.f, 0.f, 0.f);
            if (row < N) v = *(const float4*)&X[(long)row * F + k0 + kk];
            Xs[kk + 0][r] = v.x; Xs[kk + 1][r] = v.y;
            Xs[kk + 2][r] = v.z; Xs[kk + 3][r] = v.w;
        }
        // load W chunk: 16 k x 128 cols = 512 float4
#pragma unroll
        for (int it = 0; it < 2; it++) {
            int i = tid + it * 256;
            int kk = i >> 5;
            int c  = (i & 31) * 4;
            *(float4*)&Ws[kk][c] = *(const float4*)&W[(k0 + kk) * F + c];
        }
        __syncthreads();
#pragma unroll
        for (int k = 0; k < 16; k++) {
            float a[8], b[8];
            *(float4*)&a[0] = *(float4*)&Xs[k][tr];
            *(float4*)&a[4] = *(float4*)&Xs[k][tr + 4];
            *(float4*)&b[0] = *(float4*)&Ws[k][tc];
            *(float4*)&b[4] = *(float4*)&Ws[k][tc + 4];
#pragma unroll
            for (int i = 0; i < 8; i++)
#pragma unroll
                for (int j = 0; j < 8; j++) acc[i][j] += a[i] * b[j];
        }
        __syncthreads();
    }
#pragma unroll
    for (int i = 0; i < 8; i++) {
        int row = row0 + tr + i;
        if (row < N) {
            *(float4*)&Y[(long)row * F + tc]     = make_float4(acc[i][0], acc[i][1], acc[i][2], acc[i][3]);
            *(float4*)&Y[(long)row * F + tc + 4] = make_float4(acc[i][4], acc[i][5], acc[i][6], acc[i][7]);
        }
    }
}

// ---------------- layer 1 scatter -------------------------------------------
// init accumulator with self-loop term: acc[i] = dinv[i]^2 * xw[i]
__global__ void k_init_acc1(const float* __restrict__ xw, const float* __restrict__ dinv,
                            float* __restrict__ acc, int N) {
    int idx = blockIdx.x * blockDim.x + threadIdx.x;  // over N*32 float4
    if (idx >= N * 32) return;
    int node = idx >> 5;
    int j    = idx & 31;
    float s = dinv[node];
    s = s * s;
    float4 v = *(const float4*)&xw[(long)node * F + j * 4];
    v.x *= s; v.y *= s; v.z *= s; v.w *= s;
    *(float4*)&acc[(long)node * F + j * 4] = v;
}

// one warp per edge: 32 lanes x float4 = 128 floats
__global__ void k_scatter1(const int* __restrict__ row, const int* __restrict__ col,
                           const float* __restrict__ ew, const float* __restrict__ dinv,
                           const float* __restrict__ xw, float* __restrict__ acc, int E) {
    int e = blockIdx.x * (blockDim.x >> 5) + (threadIdx.x >> 5);
    if (e >= E) return;
    int lane = threadIdx.x & 31;
    int r = row[e], c = col[e];
    float nrm = dinv[r] * ew[e] * dinv[c];
    float4 v = ((const float4*)&xw[(long)r * F])[lane];
    float* dst = &acc[(long)c * F + lane * 4];
    atomicAdd(dst + 0, nrm * v.x);
    atomicAdd(dst + 1, nrm * v.y);
    atomicAdd(dst + 2, nrm * v.z);
    atomicAdd(dst + 3, nrm * v.w);
}

// h = elu(acc + b1), in place (acc lives in d_out's emb region)
__global__ void k_finalize1(float* __restrict__ acc, const float* __restrict__ b1, int N) {
    int idx = blockIdx.x * blockDim.x + threadIdx.x;
    if (idx >= N * 32) return;
    int node = idx >> 5;
    int j    = idx & 31;
    float4 v = *(float4*)&acc[(long)node * F + j * 4];
    float4 b = *(const float4*)&b1[j * 4];
    v.x += b.x; v.y += b.y; v.z += b.z; v.w += b.w;
    v.x = (v.x > 0.f) ? v.x : expm1f(v.x);
    v.y = (v.y > 0.f) ? v.y : expm1f(v.y);
    v.z = (v.z > 0.f) ? v.z : expm1f(v.z);
    v.w = (v.w > 0.f) ? v.w : expm1f(v.w);
    *(float4*)&acc[(long)node * F + j * 4] = v;
}

// ---------------- layer 2 ----------------------------------------------------
// hw[i] = dot(h[i], W2); out2 init = dinv^2 * hw
__global__ void k_hw_dot(const float* __restrict__ h, const float* __restrict__ W2,
                         const float* __restrict__ dinv, float* __restrict__ hw,
                         float* __restrict__ out2, int N) {
    int node = blockIdx.x * (blockDim.x >> 5) + (threadIdx.x >> 5);
    if (node >= N) return;
    int lane = threadIdx.x & 31;
    float4 hv = ((const float4*)&h[(long)node * F])[lane];
    float4 wv = ((const float4*)W2)[lane];
    float s = hv.x * wv.x + hv.y * wv.y + hv.z * wv.z + hv.w * wv.w;
#pragma unroll
    for (int o = 16; o > 0; o >>= 1) s += __shfl_xor_sync(0xFFFFFFFFu, s, o);
    if (lane == 0) {
        hw[node] = s;
        float d = dinv[node];
        out2[node] = d * d * s;
    }
}

__global__ void k_scatter2(const int* __restrict__ row, const int* __restrict__ col,
                           const float* __restrict__ ew, const float* __restrict__ dinv,
                           const float* __restrict__ hw, float* __restrict__ out2, int E) {
    int e = blockIdx.x * blockDim.x + threadIdx.x;
    if (e < E) {
        int r = row[e], c = col[e];
        atomicAdd(&out2[c], dinv[r] * ew[e] * dinv[c] * hw[r]);
    }
}

__global__ void k_final_out(const float* __restrict__ out2, const float* __restrict__ b2,
                            float* __restrict__ out, int N) {
    int i = blockIdx.x * blockDim.x + threadIdx.x;
    if (i < N) {
        float v = out2[i] + b2[0];
        out[i] = 1.0f / (1.0f + expf(-v));
    }
}

// ---------------- launch ------------------------------------------------------
extern "C" void kernel_launch(void* const* d_in, const int* in_sizes, int n_in,
                              void* d_out, int out_size) {
    const float* x   = (const float*)d_in[0];
    const int*   ei  = (const int*)d_in[1];     // [2, E]
    const float* ew  = (const float*)d_in[2];
    const float* W1  = (const float*)d_in[3];
    const float* b1  = (const float*)d_in[4];
    const float* W2  = (const float*)d_in[5];
    const float* b2  = (const float*)d_in[6];

    int N = in_sizes[0] / F;
    int E = in_sizes[2];
    const int* row = ei;
    const int* col = ei + E;

    float* out_pred = (float*)d_out;          // [N, 1]
    float* emb      = (float*)d_out + N;      // [N, 128] — also h and layer-1 accumulator

    float* deg  = nullptr; cudaGetSymbolAddress((void**)&deg,  g_deg);
    float* dinv = nullptr; cudaGetSymbolAddress((void**)&dinv, g_dinv);
    float* xw   = nullptr; cudaGetSymbolAddress((void**)&xw,   g_xw);
    float* hw   = nullptr; cudaGetSymbolAddress((void**)&hw,   g_hw);
    float* out2 = nullptr; cudaGetSymbolAddress((void**)&out2, g_out2);

    // normalization
    k_init_deg<<<(N + 255) / 256, 256>>>(deg, N);
    k_deg_accum<<<(E + 255) / 256, 256>>>(col, ew, deg, E);
    k_dinv<<<(N + 255) / 256, 256>>>(deg, dinv, N);

    // layer 1
    k_gemm128<<<(N + 127) / 128, 256>>>(x, W1, xw, N);
    k_init_acc1<<<(N * 32 + 255) / 256, 256>>>(xw, dinv, emb, N);
    k_scatter1<<<(E + 7) / 8, 256>>>(row, col, ew, dinv, xw, emb, E);
    k_finalize1<<<(N * 32 + 255) / 256, 256>>>(emb, b1, N);

    // layer 2
    k_hw_dot<<<(N + 7) / 8, 256>>>(emb, W2, dinv, hw, out2, N);
    k_scatter2<<<(E + 255) / 256, 256>>>(row, col, ew, dinv, hw, out2, E);
    k_final_out<<<(N + 255) / 256, 256>>>(out2, b2, out_pred, N);
}

// round 2
// speedup vs baseline: 2.4106x; 2.4106x over previous
#include <cuda_runtime.h>
#include <math.h>

#define MAX_N 100000
#define MAX_E 1600000
#define F 128
#define CHUNK 1024           // elements per scan block
#define NB ((MAX_N + CHUNK - 1) / CHUNK)

// ---------------- scratch (static device globals) ---------------------------
__device__ float g_deg[MAX_N];
__device__ float g_dinv[MAX_N];
__device__ float g_xw[MAX_N * F];       // x @ W1
__device__ float g_hw[MAX_N];           // h @ W2
__device__ int   g_count[MAX_N];        // histogram, then reused as cursor
__device__ int   g_start[MAX_N + 1];    // CSR offsets by target node
__device__ int   g_bsum[NB + 1];
__device__ int   g_srow[MAX_E];         // source row, sorted by target
__device__ float g_snrm[MAX_E];         // norm coefficient, sorted by target

// ---------------- init + degree + histogram ---------------------------------
__global__ void k_init(float* deg, int* count, int N) {
    int i = blockIdx.x * blockDim.x + threadIdx.x;
    if (i < N) { deg[i] = 1.0f; count[i] = 0; }
}

__global__ void k_edge_pass(const int* __restrict__ col, const float* __restrict__ ew,
                            float* deg, int* count, int E) {
    int e = blockIdx.x * blockDim.x + threadIdx.x;
    if (e < E) {
        int c = col[e];
        atomicAdd(&deg[c], ew[e]);
        atomicAdd(&count[c], 1);
    }
}

__global__ void k_dinv(const float* __restrict__ deg, float* dinv, int N) {
    int i = blockIdx.x * blockDim.x + threadIdx.x;
    if (i < N) {
        float d = deg[i];
        dinv[i] = (d > 0.0f) ? rsqrtf(d) : 0.0f;
    }
}

// ---------------- exclusive scan of count -> start --------------------------
__global__ void k_blocksum(const int* __restrict__ count, int* bsum, int N) {
    __shared__ int s[256];
    int base = blockIdx.x * CHUNK;
    int t = threadIdx.x;
    int local = 0;
#pragma unroll
    for (int j = 0; j < 4; j++) {
        int i = base + t * 4 + j;
        if (i < N) local += count[i];
    }
    s[t] = local;
    __syncthreads();
    for (int off = 128; off > 0; off >>= 1) {
        if (t < off) s[t] += s[t + off];
        __syncthreads();
    }
    if (t == 0) bsum[blockIdx.x] = s[0];
}

__global__ void k_scan_bsum(int* bsum, int* start, int nb, int N, int E) {
    __shared__ int s[128];
    int t = threadIdx.x;
    s[t] = (t < nb) ? bsum[t] : 0;
    __syncthreads();
    // inclusive scan (Hillis-Steele)
    for (int off = 1; off < 128; off <<= 1) {
        int x = (t >= off) ? s[t - off] : 0;
        __syncthreads();
        s[t] += x;
        __syncthreads();
    }
    if (t < nb) bsum[t] = (t > 0) ? s[t - 1] : 0;   // exclusive
    if (t == 0) start[N] = E;
}

__global__ void k_scan_scatter(int* count, const int* __restrict__ bsum,
                               int* start, int N) {
    __shared__ int s[256];
    int base = blockIdx.x * CHUNK;
    int t = threadIdx.x;
    int v[4];
    int local = 0;
#pragma unroll
    for (int j = 0; j < 4; j++) {
        int i = base + t * 4 + j;
        v[j] = (i < N) ? count[i] : 0;
        local += v[j];
    }
    s[t] = local;
    __syncthreads();
    for (int off = 1; off < 256; off <<= 1) {
        int x = (t >= off) ? s[t - off] : 0;
        __syncthreads();
        s[t] += x;
        __syncthreads();
    }
    int excl = ((t > 0) ? s[t - 1] : 0) + bsum[blockIdx.x];
#pragma unroll
    for (int j = 0; j < 4; j++) {
        int i = base + t * 4 + j;
        if (i < N) {
            start[i] = excl;
            excl += v[j];
            count[i] = 0;   // reset: reused as insertion cursor
        }
    }
}

// ---------------- permute: sort (row, nrm) by target ------------------------
__global__ void k_permute(const int* __restrict__ row, const int* __restrict__ col,
                          const float* __restrict__ ew, const float* __restrict__ dinv,
                          const int* __restrict__ start, int* count,
                          int* __restrict__ srow, float* __restrict__ snrm, int E) {
    int e = blockIdx.x * blockDim.x + threadIdx.x;
    if (e >= E) return;
    int c = col[e];
    int r = row[e];
    int pos = start[c] + atomicAdd(&count[c], 1);
    srow[pos] = r;
    snrm[pos] = dinv[r] * ew[e] * dinv[c];
}

// ---------------- SGEMM: Y[N,128] = X[N,128] @ W[128,128] -------------------
__global__ void k_gemm128(const float* __restrict__ X, const float* __restrict__ W,
                          float* __restrict__ Y, int N) {
    __shared__ float Xs[16][128];
    __shared__ float Ws[16][128];
    int tid  = threadIdx.x;
    int row0 = blockIdx.x * 128;
    int tr = (tid / 16) * 8;
    int tc = (tid % 16) * 8;

    float acc[8][8];
#pragma unroll
    for (int i = 0; i < 8; i++)
#pragma unroll
        for (int j = 0; j < 8; j++) acc[i][j] = 0.0f;

    for (int k0 = 0; k0 < 128; k0 += 16) {
#pragma unroll
        for (int it = 0; it < 2; it++) {
            int i = tid + it * 256;
            int r  = i >> 2;
            int kk = (i & 3) * 4;
            int row = row0 + r;
            float4 v = make_float4(0.f, 0.f, 0.f, 0.f);
            if (row < N) v = *(const float4*)&X[(long)row * F + k0 + kk];
            Xs[kk + 0][r] = v.x; Xs[kk + 1][r] = v.y;
            Xs[kk + 2][r] = v.z; Xs[kk + 3][r] = v.w;
        }
#pragma unroll
        for (int it = 0; it < 2; it++) {
            int i = tid + it * 256;
            int kk = i >> 5;
            int c  = (i & 31) * 4;
            *(float4*)&Ws[kk][c] = *(const float4*)&W[(k0 + kk) * F + c];
        }
        __syncthreads();
#pragma unroll
        for (int k = 0; k < 16; k++) {
            float a[8], b[8];
            *(float4*)&a[0] = *(float4*)&Xs[k][tr];
            *(float4*)&a[4] = *(float4*)&Xs[k][tr + 4];
            *(float4*)&b[0] = *(float4*)&Ws[k][tc];
            *(float4*)&b[4] = *(float4*)&Ws[k][tc + 4];
#pragma unroll
            for (int i = 0; i < 8; i++)
#pragma unroll
                for (int j = 0; j < 8; j++) acc[i][j] += a[i] * b[j];
        }
        __syncthreads();
    }
#pragma unroll
    for (int i = 0; i < 8; i++) {
        int row = row0 + tr + i;
        if (row < N) {
            *(float4*)&Y[(long)row * F + tc]     = make_float4(acc[i][0], acc[i][1], acc[i][2], acc[i][3]);
            *(float4*)&Y[(long)row * F + tc + 4] = make_float4(acc[i][4], acc[i][5], acc[i][6], acc[i][7]);
        }
    }
}

// ---------------- layer 1 gather (CSR, no atomics) --------------------------
// one warp per target node; accumulate in registers, fuse bias + ELU.
__global__ void k_gather1(const int* __restrict__ start, const int* __restrict__ srow,
                          const float* __restrict__ snrm, const float* __restrict__ xw,
                          const float* __restrict__ dinv, const float* __restrict__ b1,
                          float* __restrict__ emb, int N) {
    int node = blockIdx.x * (blockDim.x >> 5) + (threadIdx.x >> 5);
    if (node >= N) return;
    int lane = threadIdx.x & 31;

    // self-loop term
    float s = dinv[node]; s = s * s;
    float4 acc = ((const float4*)&xw[(long)node * F])[lane];
    acc.x *= s; acc.y *= s; acc.z *= s; acc.w *= s;

    int e  = start[node];
    int e1 = start[node + 1];
    // unroll-2 for MLP
    for (; e + 1 < e1; e += 2) {
        int   r0 = srow[e],     r1 = srow[e + 1];
        float n0 = snrm[e],     n1 = snrm[e + 1];
        float4 v0 = ((const float4*)&xw[(long)r0 * F])[lane];
        float4 v1 = ((const float4*)&xw[(long)r1 * F])[lane];
        acc.x += n0 * v0.x + n1 * v1.x;
        acc.y += n0 * v0.y + n1 * v1.y;
        acc.z += n0 * v0.z + n1 * v1.z;
        acc.w += n0 * v0.w + n1 * v1.w;
    }
    if (e < e1) {
        int   r0 = srow[e];
        float n0 = snrm[e];
        float4 v0 = ((const float4*)&xw[(long)r0 * F])[lane];
        acc.x += n0 * v0.x; acc.y += n0 * v0.y;
        acc.z += n0 * v0.z; acc.w += n0 * v0.w;
    }

    float4 b = ((const float4*)b1)[lane];
    acc.x += b.x; acc.y += b.y; acc.z += b.z; acc.w += b.w;
    acc.x = (acc.x > 0.f) ? acc.x : expm1f(acc.x);
    acc.y = (acc.y > 0.f) ? acc.y : expm1f(acc.y);
    acc.z = (acc.z > 0.f) ? acc.z : expm1f(acc.z);
    acc.w = (acc.w > 0.f) ? acc.w : expm1f(acc.w);
    ((float4*)&emb[(long)node * F])[lane] = acc;
}

// ---------------- layer 2 ----------------------------------------------------
__global__ void k_hw_dot(const float* __restrict__ h, const float* __restrict__ W2,
                         float* __restrict__ hw, int N) {
    int node = blockIdx.x * (blockDim.x >> 5) + (threadIdx.x >> 5);
    if (node >= N) return;
    int lane = threadIdx.x & 31;
    float4 hv = ((const float4*)&h[(long)node * F])[lane];
    float4 wv = ((const float4*)W2)[lane];
    float s = hv.x * wv.x + hv.y * wv.y + hv.z * wv.z + hv.w * wv.w;
#pragma unroll
    for (int o = 16; o > 0; o >>= 1) s += __shfl_xor_sync(0xFFFFFFFFu, s, o);
    if (lane == 0) hw[node] = s;
}

// one thread per node: CSR gather + self-loop + bias + sigmoid
__global__ void k_gather2(const int* __restrict__ start, const int* __restrict__ srow,
                          const float* __restrict__ snrm, const float* __restrict__ hw,
                          const float* __restrict__ dinv, const float* __restrict__ b2,
                          float* __restrict__ out, int N) {
    int node = blockIdx.x * blockDim.x + threadIdx.x;
    if (node >= N) return;
    float d = dinv[node];
    float sum = d * d * hw[node];
    int e  = start[node];
    int e1 = start[node + 1];
    for (; e + 1 < e1; e += 2) {
        sum += snrm[e] * hw[srow[e]] + snrm[e + 1] * hw[srow[e + 1]];
    }
    if (e < e1) sum += snrm[e] * hw[srow[e]];
    float v = sum + b2[0];
    out[node] = 1.0f / (1.0f + expf(-v));
}

// ---------------- launch ------------------------------------------------------
extern "C" void kernel_launch(void* const* d_in, const int* in_sizes, int n_in,
                              void* d_out, int out_size) {
    const float* x   = (const float*)d_in[0];
    const int*   ei  = (const int*)d_in[1];     // [2, E]
    const float* ew  = (const float*)d_in[2];
    const float* W1  = (const float*)d_in[3];
    const float* b1  = (const float*)d_in[4];
    const float* W2  = (const float*)d_in[5];
    const float* b2  = (const float*)d_in[6];

    int N = in_sizes[0] / F;
    int E = in_sizes[2];
    const int* row = ei;
    const int* col = ei + E;

    float* out_pred = (float*)d_out;          // [N, 1]
    float* emb      = (float*)d_out + N;      // [N, 128]

    float* deg   = nullptr; cudaGetSymbolAddress((void**)&deg,   g_deg);
    float* dinv  = nullptr; cudaGetSymbolAddress((void**)&dinv,  g_dinv);
    float* xw    = nullptr; cudaGetSymbolAddress((void**)&xw,    g_xw);
    float* hw    = nullptr; cudaGetSymbolAddress((void**)&hw,    g_hw);
    int*   count = nullptr; cudaGetSymbolAddress((void**)&count, g_count);
    int*   start = nullptr; cudaGetSymbolAddress((void**)&start, g_start);
    int*   bsum  = nullptr; cudaGetSymbolAddress((void**)&bsum,  g_bsum);
    int*   srow  = nullptr; cudaGetSymbolAddress((void**)&srow,  g_srow);
    float* snrm  = nullptr; cudaGetSymbolAddress((void**)&snrm,  g_snrm);

    int nb = (N + CHUNK - 1) / CHUNK;

    // GEMM is independent of graph structure — issue first
    k_gemm128<<<(N + 127) / 128, 256>>>(x, W1, xw, N);

    // degree + histogram + normalization
    k_init<<<(N + 255) / 256, 256>>>(deg, count, N);
    k_edge_pass<<<(E + 255) / 256, 256>>>(col, ew, deg, count, E);
    k_dinv<<<(N + 255) / 256, 256>>>(deg, dinv, N);

    // CSR offsets
    k_blocksum<<<nb, 256>>>(count, bsum, N);
    k_scan_bsum<<<1, 128>>>(bsum, start, nb, N, E);
    k_scan_scatter<<<nb, 256>>>(count, bsum, start, N);

    // sorted (row, nrm)
    k_permute<<<(E + 255) / 256, 256>>>(row, col, ew, dinv, start, count, srow, snrm, E);

    // layer 1: gather + bias + ELU
    k_gather1<<<(N + 7) / 8, 256>>>(start, srow, snrm, xw, dinv, b1, emb, N);

    // layer 2
    k_hw_dot<<<(N + 7) / 8, 256>>>(emb, W2, hw, N);
    k_gather2<<<(N + 255) / 256, 256>>>(start, srow, snrm, hw, dinv, b2, out_pred, N);
}

// round 3
// speedup vs baseline: 2.5122x; 1.0422x over previous
#include <cuda_runtime.h>
#include <math.h>

#define MAX_N 100000
#define MAX_E 1600000
#define F 128
#define CHUNK 1024           // elements per scan block
#define NB ((MAX_N + CHUNK - 1) / CHUNK)

// ---------------- scratch (static device globals) ---------------------------
__device__ float g_deg[MAX_N];
__device__ float g_dinv[MAX_N];
__device__ float g_xw[MAX_N * F];       // x @ W1
__device__ float g_hw[MAX_N];           // h @ W2
__device__ int   g_count[MAX_N];        // histogram, then reused as cursor
__device__ int   g_start[MAX_N + 1];    // CSR offsets by target node
__device__ int   g_bsum[NB + 1];
__device__ int   g_srow[MAX_E];         // source row, sorted by target
__device__ float g_snrm[MAX_E];         // norm coefficient, sorted by target

// ---------------- init + degree + histogram ---------------------------------
__global__ void k_init(float* deg, int* count, int N) {
    int i = blockIdx.x * blockDim.x + threadIdx.x;
    if (i < N) { deg[i] = 1.0f; count[i] = 0; }
}

__global__ void k_edge_pass(const int* __restrict__ col, const float* __restrict__ ew,
                            float* deg, int* count, int E) {
    int e = blockIdx.x * blockDim.x + threadIdx.x;
    if (e < E) {
        int c = col[e];
        atomicAdd(&deg[c], ew[e]);
        atomicAdd(&count[c], 1);
    }
}

__global__ void k_dinv(const float* __restrict__ deg, float* dinv, int N) {
    int i = blockIdx.x * blockDim.x + threadIdx.x;
    if (i < N) {
        float d = deg[i];
        dinv[i] = (d > 0.0f) ? rsqrtf(d) : 0.0f;
    }
}

// ---------------- exclusive scan of count -> start --------------------------
__global__ void k_blocksum(const int* __restrict__ count, int* bsum, int N) {
    __shared__ int s[256];
    int base = blockIdx.x * CHUNK;
    int t = threadIdx.x;
    int local = 0;
#pragma unroll
    for (int j = 0; j < 4; j++) {
        int i = base + t * 4 + j;
        if (i < N) local += count[i];
    }
    s[t] = local;
    __syncthreads();
    for (int off = 128; off > 0; off >>= 1) {
        if (t < off) s[t] += s[t + off];
        __syncthreads();
    }
    if (t == 0) bsum[blockIdx.x] = s[0];
}

__global__ void k_scan_bsum(int* bsum, int* start, int nb, int N, int E) {
    __shared__ int s[128];
    int t = threadIdx.x;
    s[t] = (t < nb) ? bsum[t] : 0;
    __syncthreads();
    for (int off = 1; off < 128; off <<= 1) {
        int x = (t >= off) ? s[t - off] : 0;
        __syncthreads();
        s[t] += x;
        __syncthreads();
    }
    if (t < nb) bsum[t] = (t > 0) ? s[t - 1] : 0;   // exclusive
    if (t == 0) start[N] = E;
}

__global__ void k_scan_scatter(int* count, const int* __restrict__ bsum,
                               int* start, int N) {
    __shared__ int s[256];
    int base = blockIdx.x * CHUNK;
    int t = threadIdx.x;
    int v[4];
    int local = 0;
#pragma unroll
    for (int j = 0; j < 4; j++) {
        int i = base + t * 4 + j;
        v[j] = (i < N) ? count[i] : 0;
        local += v[j];
    }
    s[t] = local;
    __syncthreads();
    for (int off = 1; off < 256; off <<= 1) {
        int x = (t >= off) ? s[t - off] : 0;
        __syncthreads();
        s[t] += x;
        __syncthreads();
    }
    int excl = ((t > 0) ? s[t - 1] : 0) + bsum[blockIdx.x];
#pragma unroll
    for (int j = 0; j < 4; j++) {
        int i = base + t * 4 + j;
        if (i < N) {
            start[i] = excl;
            excl += v[j];
            count[i] = 0;   // reset: reused as insertion cursor
        }
    }
}

// ---------------- permute: sort (row, nrm) by target ------------------------
__global__ void k_permute(const int* __restrict__ row, const int* __restrict__ col,
                          const float* __restrict__ ew, const float* __restrict__ dinv,
                          const int* __restrict__ start, int* count,
                          int* __restrict__ srow, float* __restrict__ snrm, int E) {
    int e = blockIdx.x * blockDim.x + threadIdx.x;
    if (e >= E) return;
    int c = col[e];
    int r = row[e];
    int pos = start[c] + atomicAdd(&count[c], 1);
    srow[pos] = r;
    snrm[pos] = dinv[r] * ew[e] * dinv[c];
}

// ---------------- SGEMM: Y[N,128] = X[N,128] @ W[128,128] -------------------
// 128x128 tile, 256 threads, 8x8 micro-tile, double-buffered k-chunks of 16.
__global__ void __launch_bounds__(256, 2)
k_gemm128(const float* __restrict__ X, const float* __restrict__ W,
          float* __restrict__ Y, int N) {
    __shared__ float Xs[2][16][128];
    __shared__ float Ws[2][16][128];
    int tid  = threadIdx.x;
    int row0 = blockIdx.x * 128;
    int tr = (tid / 16) * 8;
    int tc = (tid % 16) * 8;

    // per-thread load coordinates (2 float4 each for X and W)
    int xi0 = tid, xi1 = tid + 256;
    int xr0 = xi0 >> 2, xk0 = (xi0 & 3) * 4;
    int xr1 = xi1 >> 2, xk1 = (xi1 & 3) * 4;
    int wi0 = tid, wi1 = tid + 256;
    int wk0 = wi0 >> 5, wc0 = (wi0 & 31) * 4;
    int wk1 = wi1 >> 5, wc1 = (wi1 & 31) * 4;

    float acc[8][8];
#pragma unroll
    for (int i = 0; i < 8; i++)
#pragma unroll
        for (int j = 0; j < 8; j++) acc[i][j] = 0.0f;

    float4 xv0, xv1, wv0, wv1;

    // fetch chunk c into registers
    auto fetch = [&](int c) {
        int k0 = c * 16;
        int r0g = row0 + xr0, r1g = row0 + xr1;
        xv0 = (r0g < N) ? *(const float4*)&X[(long)r0g * F + k0 + xk0] : make_float4(0,0,0,0);
        xv1 = (r1g < N) ? *(const float4*)&X[(long)r1g * F + k0 + xk1] : make_float4(0,0,0,0);
        wv0 = *(const float4*)&W[(k0 + wk0) * F + wc0];
        wv1 = *(const float4*)&W[(k0 + wk1) * F + wc1];
    };
    // store registers into buffer b
    auto stage = [&](int b) {
        Xs[b][xk0 + 0][xr0] = xv0.x; Xs[b][xk0 + 1][xr0] = xv0.y;
        Xs[b][xk0 + 2][xr0] = xv0.z; Xs[b][xk0 + 3][xr0] = xv0.w;
        Xs[b][xk1 + 0][xr1] = xv1.x; Xs[b][xk1 + 1][xr1] = xv1.y;
        Xs[b][xk1 + 2][xr1] = xv1.z; Xs[b][xk1 + 3][xr1] = xv1.w;
        *(float4*)&Ws[b][wk0][wc0] = wv0;
        *(float4*)&Ws[b][wk1][wc1] = wv1;
    };

    fetch(0);
    stage(0);
    __syncthreads();

    int p = 0;
#pragma unroll
    for (int c = 0; c < 8; c++) {
        if (c < 7) fetch(c + 1);     // issue global loads early
#pragma unroll
        for (int k = 0; k < 16; k++) {
            float a[8], b[8];
            *(float4*)&a[0] = *(float4*)&Xs[p][k][tr];
            *(float4*)&a[4] = *(float4*)&Xs[p][k][tr + 4];
            *(float4*)&b[0] = *(float4*)&Ws[p][k][tc];
            *(float4*)&b[4] = *(float4*)&Ws[p][k][tc + 4];
#pragma unroll
            for (int i = 0; i < 8; i++)
#pragma unroll
                for (int j = 0; j < 8; j++) acc[i][j] += a[i] * b[j];
        }
        if (c < 7) {
            stage(1 - p);
            __syncthreads();
            p ^= 1;
        }
    }
#pragma unroll
    for (int i = 0; i < 8; i++) {
        int row = row0 + tr + i;
        if (row < N) {
            *(float4*)&Y[(long)row * F + tc]     = make_float4(acc[i][0], acc[i][1], acc[i][2], acc[i][3]);
            *(float4*)&Y[(long)row * F + tc + 4] = make_float4(acc[i][4], acc[i][5], acc[i][6], acc[i][7]);
        }
    }
}

// ---------------- layer 1 gather (CSR, no atomics) + fused h@W2 -------------
// one warp per target node; accumulate in registers, fuse bias + ELU + W2 dot.
__global__ void k_gather1(const int* __restrict__ start, const int* __restrict__ srow,
                          const float* __restrict__ snrm, const float* __restrict__ xw,
                          const float* __restrict__ dinv, const float* __restrict__ b1,
                          const float* __restrict__ W2,
                          float* __restrict__ emb, float* __restrict__ hw, int N) {
    int node = blockIdx.x * (blockDim.x >> 5) + (threadIdx.x >> 5);
    if (node >= N) return;
    int lane = threadIdx.x & 31;

    // self-loop term
    float s = dinv[node]; s = s * s;
    float4 acc = ((const float4*)&xw[(long)node * F])[lane];
    acc.x *= s; acc.y *= s; acc.z *= s; acc.w *= s;

    int e  = start[node];
    int e1 = start[node + 1];
    // unroll-4 for MLP
    for (; e + 3 < e1; e += 4) {
        int   r0 = srow[e],   r1 = srow[e+1], r2 = srow[e+2], r3 = srow[e+3];
        float n0 = snrm[e],   n1 = snrm[e+1], n2 = snrm[e+2], n3 = snrm[e+3];
        float4 v0 = ((const float4*)&xw[(long)r0 * F])[lane];
        float4 v1 = ((const float4*)&xw[(long)r1 * F])[lane];
        float4 v2 = ((const float4*)&xw[(long)r2 * F])[lane];
        float4 v3 = ((const float4*)&xw[(long)r3 * F])[lane];
        acc.x += n0*v0.x + n1*v1.x + n2*v2.x + n3*v3.x;
        acc.y += n0*v0.y + n1*v1.y + n2*v2.y + n3*v3.y;
        acc.z += n0*v0.z + n1*v1.z + n2*v2.z + n3*v3.z;
        acc.w += n0*v0.w + n1*v1.w + n2*v2.w + n3*v3.w;
    }
    for (; e < e1; e++) {
        int   r0 = srow[e];
        float n0 = snrm[e];
        float4 v0 = ((const float4*)&xw[(long)r0 * F])[lane];
        acc.x += n0 * v0.x; acc.y += n0 * v0.y;
        acc.z += n0 * v0.z; acc.w += n0 * v0.w;
    }

    float4 b = ((const float4*)b1)[lane];
    acc.x += b.x; acc.y += b.y; acc.z += b.z; acc.w += b.w;
    acc.x = (acc.x > 0.f) ? acc.x : expm1f(acc.x);
    acc.y = (acc.y > 0.f) ? acc.y : expm1f(acc.y);
    acc.z = (acc.z > 0.f) ? acc.z : expm1f(acc.z);
    acc.w = (acc.w > 0.f) ? acc.w : expm1f(acc.w);
    ((float4*)&emb[(long)node * F])[lane] = acc;

    // fused h @ W2 (h is in registers)
    float4 wv = ((const float4*)W2)[lane];
    float d = acc.x * wv.x + acc.y * wv.y + acc.z * wv.z + acc.w * wv.w;
#pragma unroll
    for (int o = 16; o > 0; o >>= 1) d += __shfl_xor_sync(0xFFFFFFFFu, d, o);
    if (lane == 0) hw[node] = d;
}

// ---------------- layer 2: CSR gather + self-loop + bias + sigmoid ----------
__global__ void k_gather2(const int* __restrict__ start, const int* __restrict__ srow,
                          const float* __restrict__ snrm, const float* __restrict__ hw,
                          const float* __restrict__ dinv, const float* __restrict__ b2,
                          float* __restrict__ out, int N) {
    int node = blockIdx.x * blockDim.x + threadIdx.x;
    if (node >= N) return;
    float d = dinv[node];
    float sum = d * d * hw[node];
    int e  = start[node];
    int e1 = start[node + 1];
    for (; e + 1 < e1; e += 2) {
        sum += snrm[e] * hw[srow[e]] + snrm[e + 1] * hw[srow[e + 1]];
    }
    if (e < e1) sum += snrm[e] * hw[srow[e]];
    float v = sum + b2[0];
    out[node] = 1.0f / (1.0f + expf(-v));
}

// ---------------- launch ------------------------------------------------------
extern "C" void kernel_launch(void* const* d_in, const int* in_sizes, int n_in,
                              void* d_out, int out_size) {
    const float* x   = (const float*)d_in[0];
    const int*   ei  = (const int*)d_in[1];     // [2, E]
    const float* ew  = (const float*)d_in[2];
    const float* W1  = (const float*)d_in[3];
    const float* b1  = (const float*)d_in[4];
    const float* W2  = (const float*)d_in[5];
    const float* b2  = (const float*)d_in[6];

    int N = in_sizes[0] / F;
    int E = in_sizes[2];
    const int* row = ei;
    const int* col = ei + E;

    float* out_pred = (float*)d_out;          // [N, 1]
    float* emb      = (float*)d_out + N;      // [N, 128]

    float* deg   = nullptr; cudaGetSymbolAddress((void**)&deg,   g_deg);
    float* dinv  = nullptr; cudaGetSymbolAddress((void**)&dinv,  g_dinv);
    float* xw    = nullptr; cudaGetSymbolAddress((void**)&xw,    g_xw);
    float* hw    = nullptr; cudaGetSymbolAddress((void**)&hw,    g_hw);
    int*   count = nullptr; cudaGetSymbolAddress((void**)&count, g_count);
    int*   start = nullptr; cudaGetSymbolAddress((void**)&start, g_start);
    int*   bsum  = nullptr; cudaGetSymbolAddress((void**)&bsum,  g_bsum);
    int*   srow  = nullptr; cudaGetSymbolAddress((void**)&srow,  g_srow);
    float* snrm  = nullptr; cudaGetSymbolAddress((void**)&snrm,  g_snrm);

    int nb = (N + CHUNK - 1) / CHUNK;

    // side stream + fork/join events (host resources, created once)
    static cudaStream_t s2 = nullptr;
    static cudaEvent_t ev_fork = nullptr, ev_join = nullptr;
    if (s2 == nullptr) {
        cudaStreamCreateWithFlags(&s2, cudaStreamNonBlocking);
        cudaEventCreateWithFlags(&ev_fork, cudaEventDisableTiming);
        cudaEventCreateWithFlags(&ev_join, cudaEventDisableTiming);
    }

    // fork: CSR build on s2 runs concurrently with the GEMM on the main stream
    cudaEventRecord(ev_fork, 0);
    cudaStreamWaitEvent(s2, ev_fork, 0);

    // main stream: GEMM (independent of graph structure)
    k_gemm128<<<(N + 127) / 128, 256>>>(x, W1, xw, N);

    // s2: degree + histogram + normalization + CSR + permute
    k_init<<<(N + 255) / 256, 256, 0, s2>>>(deg, count, N);
    k_edge_pass<<<(E + 255) / 256, 256, 0, s2>>>(col, ew, deg, count, E);
    k_dinv<<<(N + 255) / 256, 256, 0, s2>>>(deg, dinv, N);
    k_blocksum<<<nb, 256, 0, s2>>>(count, bsum, N);
    k_scan_bsum<<<1, 128, 0, s2>>>(bsum, start, nb, N, E);
    k_scan_scatter<<<nb, 256, 0, s2>>>(count, bsum, start, N);
    k_permute<<<(E + 255) / 256, 256, 0, s2>>>(row, col, ew, dinv, start, count, srow, snrm, E);

    // join
    cudaEventRecord(ev_join, s2);
    cudaStreamWaitEvent(0, ev_join, 0);

    // layer 1: gather + bias + ELU + fused h@W2
    k_gather1<<<(N + 7) / 8, 256>>>(start, srow, snrm, xw, dinv, b1, W2, emb, hw, N);

    // layer 2
    k_gather2<<<(N + 255) / 256, 256>>>(start, srow, snrm, hw, dinv, b2, out_pred, N);
}

// round 4
// speedup vs baseline: 2.9721x; 1.1831x over previous
#include <cuda_runtime.h>
#include <math.h>
#include <stdint.h>

#define MAX_N 100000
#define MAX_E 1600000
#define F 128
#define CHUNK 1024
#define NB ((MAX_N + CHUNK - 1) / CHUNK)
#define WPAD 136   // smem row stride for W tiles (conflict-free fragment loads)

// ---------------- scratch (static device globals) ---------------------------
__device__ float g_deg[MAX_N];
__device__ float g_dinv[MAX_N];
__device__ float g_xw[MAX_N * F];
__device__ float g_hw[MAX_N];
__device__ int   g_count[MAX_N];
__device__ int   g_start[MAX_N + 1];
__device__ int   g_bsum[NB + 1];
__device__ int   g_srow[MAX_E];
__device__ float g_snrm[MAX_E];
__device__ float g_w1hi[F * F];
__device__ float g_w1lo[F * F];

// ---------------- init + degree + histogram ---------------------------------
__global__ void k_init(float* deg, int* count, int N) {
    int i = blockIdx.x * blockDim.x + threadIdx.x;
    if (i < N) { deg[i] = 1.0f; count[i] = 0; }
}

__global__ void k_edge_pass(const int* __restrict__ col, const float* __restrict__ ew,
                            float* deg, int* count, int E) {
    int e = blockIdx.x * blockDim.x + threadIdx.x;
    if (e < E) {
        int c = col[e];
        atomicAdd(&deg[c], ew[e]);
        atomicAdd(&count[c], 1);
    }
}

__global__ void k_dinv(const float* __restrict__ deg, float* dinv, int N) {
    int i = blockIdx.x * blockDim.x + threadIdx.x;
    if (i < N) {
        float d = deg[i];
        dinv[i] = (d > 0.0f) ? rsqrtf(d) : 0.0f;
    }
}

// ---------------- exclusive scan of count -> start --------------------------
__global__ void k_blocksum(const int* __restrict__ count, int* bsum, int N) {
    __shared__ int s[256];
    int base = blockIdx.x * CHUNK;
    int t = threadIdx.x;
    int local = 0;
#pragma unroll
    for (int j = 0; j < 4; j++) {
        int i = base + t * 4 + j;
        if (i < N) local += count[i];
    }
    s[t] = local;
    __syncthreads();
    for (int off = 128; off > 0; off >>= 1) {
        if (t < off) s[t] += s[t + off];
        __syncthreads();
    }
    if (t == 0) bsum[blockIdx.x] = s[0];
}

__global__ void k_scan_bsum(int* bsum, int* start, int nb, int N, int E) {
    __shared__ int s[128];
    int t = threadIdx.x;
    s[t] = (t < nb) ? bsum[t] : 0;
    __syncthreads();
    for (int off = 1; off < 128; off <<= 1) {
        int x = (t >= off) ? s[t - off] : 0;
        __syncthreads();
        s[t] += x;
        __syncthreads();
    }
    if (t < nb) bsum[t] = (t > 0) ? s[t - 1] : 0;
    if (t == 0) start[N] = E;
}

__global__ void k_scan_scatter(int* count, const int* __restrict__ bsum,
                               int* start, int N) {
    __shared__ int s[256];
    int base = blockIdx.x * CHUNK;
    int t = threadIdx.x;
    int v[4];
    int local = 0;
#pragma unroll
    for (int j = 0; j < 4; j++) {
        int i = base + t * 4 + j;
        v[j] = (i < N) ? count[i] : 0;
        local += v[j];
    }
    s[t] = local;
    __syncthreads();
    for (int off = 1; off < 256; off <<= 1) {
        int x = (t >= off) ? s[t - off] : 0;
        __syncthreads();
        s[t] += x;
        __syncthreads();
    }
    int excl = ((t > 0) ? s[t - 1] : 0) + bsum[blockIdx.x];
#pragma unroll
    for (int j = 0; j < 4; j++) {
        int i = base + t * 4 + j;
        if (i < N) {
            start[i] = excl;
            excl += v[j];
            count[i] = 0;
        }
    }
}

// ---------------- permute: sort (row, nrm) by target ------------------------
__global__ void k_permute(const int* __restrict__ row, const int* __restrict__ col,
                          const float* __restrict__ ew, const float* __restrict__ dinv,
                          const int* __restrict__ start, int* count,
                          int* __restrict__ srow, float* __restrict__ snrm, int E) {
    int e = blockIdx.x * blockDim.x + threadIdx.x;
    if (e >= E) return;
    int c = col[e];
    int r = row[e];
    int pos = start[c] + atomicAdd(&count[c], 1);
    srow[pos] = r;
    snrm[pos] = dinv[r] * ew[e] * dinv[c];
}

// ---------------- W1 split into tf32 hi/lo -----------------------------------
__device__ __forceinline__ uint32_t f2tf32(float v) {
    uint32_t r;
    asm("cvt.rna.tf32.f32 %0, %1;" : "=r"(r) : "f"(v));
    return r;
}

__global__ void k_split_w(const float* __restrict__ W, float* __restrict__ Wh,
                          float* __restrict__ Wl) {
    int i = blockIdx.x * blockDim.x + threadIdx.x;
    if (i >= F * F) return;
    float w = W[i];
    float hf = __uint_as_float(f2tf32(w));
    float lof = __uint_as_float(f2tf32(w - hf));
    Wh[i] = hf;
    Wl[i] = lof;
}

// ---------------- tf32 tensor-core GEMM: Y = X @ W1 (3xTF32) ------------------
// block 128x128, 8 warps (4 row-groups x 2 col-groups), warp = 32 rows x 64 cols
__global__ void __launch_bounds__(256, 2)
k_gemm_tf32(const float* __restrict__ X, const float* __restrict__ Wh_g,
            const float* __restrict__ Wl_g, float* __restrict__ Y, int N) {
    __shared__ float Xs[2][128][8];
    __shared__ float Wh[2][8][WPAD];
    __shared__ float Wl[2][8][WPAD];

    int tid  = threadIdx.x;
    int lane = tid & 31;
    int wid  = tid >> 5;
    int wr   = wid >> 1;          // 0..3  (32-row group)
    int wc   = wid & 1;           // 0..1  (64-col group)
    int g    = lane >> 2;         // 0..7
    int tig  = lane & 3;          // 0..3
    int row0 = blockIdx.x * 128;

    // global load coords
    int xrow = tid >> 1;              // 0..127
    int xoff = (tid & 1) * 4;         // 0 or 4
    int wkr  = tid >> 5;              // 0..7
    int wcc  = (tid & 31) * 4;        // 0..124

    float4 xv, whv, wlv;

    float acc[2][8][4];
#pragma unroll
    for (int rt = 0; rt < 2; rt++)
#pragma unroll
        for (int nt = 0; nt < 8; nt++)
#pragma unroll
            for (int j = 0; j < 4; j++) acc[rt][nt][j] = 0.0f;

    // fetch chunk c into registers
    {
        int gr = row0 + xrow;
        xv = (gr < N) ? *(const float4*)&X[(long)gr * F + xoff] : make_float4(0,0,0,0);
        whv = *(const float4*)&Wh_g[wkr * F + wcc];
        wlv = *(const float4*)&Wl_g[wkr * F + wcc];
        *(float4*)&Xs[0][xrow][xoff] = xv;
        *(float4*)&Wh[0][wkr][wcc] = whv;
        *(float4*)&Wl[0][wkr][wcc] = wlv;
    }
    __syncthreads();

    int p = 0;
#pragma unroll
    for (int c = 0; c < 16; c++) {
        if (c < 15) {
            int k0 = (c + 1) * 8;
            int gr = row0 + xrow;
            xv = (gr < N) ? *(const float4*)&X[(long)gr * F + k0 + xoff] : make_float4(0,0,0,0);
            whv = *(const float4*)&Wh_g[(k0 + wkr) * F + wcc];
            wlv = *(const float4*)&Wl_g[(k0 + wkr) * F + wcc];
        }

        // A fragments (2 m16 row-tiles), split hi/lo
        uint32_t ah[2][4], al[2][4];
#pragma unroll
        for (int rt = 0; rt < 2; rt++) {
            int rb = wr * 32 + rt * 16;
            float a0 = Xs[p][rb + g][tig];
            float a1 = Xs[p][rb + g + 8][tig];
            float a2 = Xs[p][rb + g][tig + 4];
            float a3 = Xs[p][rb + g + 8][tig + 4];
            ah[rt][0] = f2tf32(a0); al[rt][0] = f2tf32(a0 - __uint_as_float(ah[rt][0]));
            ah[rt][1] = f2tf32(a1); al[rt][1] = f2tf32(a1 - __uint_as_float(ah[rt][1]));
            ah[rt][2] = f2tf32(a2); al[rt][2] = f2tf32(a2 - __uint_as_float(ah[rt][2]));
            ah[rt][3] = f2tf32(a3); al[rt][3] = f2tf32(a3 - __uint_as_float(ah[rt][3]));
        }

#pragma unroll
        for (int nt = 0; nt < 8; nt++) {
            int cb = wc * 64 + nt * 8;
            uint32_t bh0 = __float_as_uint(Wh[p][tig][cb + g]);
            uint32_t bh1 = __float_as_uint(Wh[p][tig + 4][cb + g]);
            uint32_t bl0 = __float_as_uint(Wl[p][tig][cb + g]);
            uint32_t bl1 = __float_as_uint(Wl[p][tig + 4][cb + g]);
#pragma unroll
            for (int rt = 0; rt < 2; rt++) {
                float* d = acc[rt][nt];
                asm volatile(
                    "mma.sync.aligned.m16n8k8.row.col.f32.tf32.tf32.f32 "
                    "{%0,%1,%2,%3}, {%4,%5,%6,%7}, {%8,%9}, {%0,%1,%2,%3};"
                    : "+f"(d[0]), "+f"(d[1]), "+f"(d[2]), "+f"(d[3])
                    : "r"(ah[rt][0]), "r"(ah[rt][1]), "r"(ah[rt][2]), "r"(ah[rt][3]),
                      "r"(bh0), "r"(bh1));
                asm volatile(
                    "mma.sync.aligned.m16n8k8.row.col.f32.tf32.tf32.f32 "
                    "{%0,%1,%2,%3}, {%4,%5,%6,%7}, {%8,%9}, {%0,%1,%2,%3};"
                    : "+f"(d[0]), "+f"(d[1]), "+f"(d[2]), "+f"(d[3])
                    : "r"(ah[rt][0]), "r"(ah[rt][1]), "r"(ah[rt][2]), "r"(ah[rt][3]),
                      "r"(bl0), "r"(bl1));
                asm volatile(
                    "mma.sync.aligned.m16n8k8.row.col.f32.tf32.tf32.f32 "
                    "{%0,%1,%2,%3}, {%4,%5,%6,%7}, {%8,%9}, {%0,%1,%2,%3};"
                    : "+f"(d[0]), "+f"(d[1]), "+f"(d[2]), "+f"(d[3])
                    : "r"(al[rt][0]), "r"(al[rt][1]), "r"(al[rt][2]), "r"(al[rt][3]),
                      "r"(bh0), "r"(bh1));
            }
        }

        if (c < 15) {
            int b = 1 - p;
            *(float4*)&Xs[b][xrow][xoff] = xv;
            *(float4*)&Wh[b][wkr][wcc] = whv;
            *(float4*)&Wl[b][wkr][wcc] = wlv;
            __syncthreads();
            p ^= 1;
        }
    }

    // epilogue: c0,c1 -> row g; c2,c3 -> row g+8; cols cb+2*tig, +1
#pragma unroll
    for (int rt = 0; rt < 2; rt++) {
        int r0g = row0 + wr * 32 + rt * 16 + g;
        int r1g = r0g + 8;
#pragma unroll
        for (int nt = 0; nt < 8; nt++) {
            int cc = wc * 64 + nt * 8 + 2 * tig;
            if (r0g < N) {
                Y[(long)r0g * F + cc]     = acc[rt][nt][0];
                Y[(long)r0g * F + cc + 1] = acc[rt][nt][1];
            }
            if (r1g < N) {
                Y[(long)r1g * F + cc]     = acc[rt][nt][2];
                Y[(long)r1g * F + cc + 1] = acc[rt][nt][3];
            }
        }
    }
}

// ---------------- layer 1 gather (CSR) + fused h@W2 --------------------------
__global__ void k_gather1(const int* __restrict__ start, const int* __restrict__ srow,
                          const float* __restrict__ snrm, const float* __restrict__ xw,
                          const float* __restrict__ dinv, const float* __restrict__ b1,
                          const float* __restrict__ W2,
                          float* __restrict__ emb, float* __restrict__ hw, int N) {
    int node = blockIdx.x * (blockDim.x >> 5) + (threadIdx.x >> 5);
    if (node >= N) return;
    int lane = threadIdx.x & 31;

    float s = dinv[node]; s = s * s;
    float4 acc = ((const float4*)&xw[(long)node * F])[lane];
    acc.x *= s; acc.y *= s; acc.z *= s; acc.w *= s;

    int e  = start[node];
    int e1 = start[node + 1];
    for (; e + 3 < e1; e += 4) {
        int   r0 = srow[e],   r1 = srow[e+1], r2 = srow[e+2], r3 = srow[e+3];
        float n0 = snrm[e],   n1 = snrm[e+1], n2 = snrm[e+2], n3 = snrm[e+3];
        float4 v0 = ((const float4*)&xw[(long)r0 * F])[lane];
        float4 v1 = ((const float4*)&xw[(long)r1 * F])[lane];
        float4 v2 = ((const float4*)&xw[(long)r2 * F])[lane];
        float4 v3 = ((const float4*)&xw[(long)r3 * F])[lane];
        acc.x += n0*v0.x + n1*v1.x + n2*v2.x + n3*v3.x;
        acc.y += n0*v0.y + n1*v1.y + n2*v2.y + n3*v3.y;
        acc.z += n0*v0.z + n1*v1.z + n2*v2.z + n3*v3.z;
        acc.w += n0*v0.w + n1*v1.w + n2*v2.w + n3*v3.w;
    }
    for (; e < e1; e++) {
        int   r0 = srow[e];
        float n0 = snrm[e];
        float4 v0 = ((const float4*)&xw[(long)r0 * F])[lane];
        acc.x += n0 * v0.x; acc.y += n0 * v0.y;
        acc.z += n0 * v0.z; acc.w += n0 * v0.w;
    }

    float4 b = ((const float4*)b1)[lane];
    acc.x += b.x; acc.y += b.y; acc.z += b.z; acc.w += b.w;
    acc.x = (acc.x > 0.f) ? acc.x : expm1f(acc.x);
    acc.y = (acc.y > 0.f) ? acc.y : expm1f(acc.y);
    acc.z = (acc.z > 0.f) ? acc.z : expm1f(acc.z);
    acc.w = (acc.w > 0.f) ? acc.w : expm1f(acc.w);
    ((float4*)&emb[(long)node * F])[lane] = acc;

    float4 wv = ((const float4*)W2)[lane];
    float d = acc.x * wv.x + acc.y * wv.y + acc.z * wv.z + acc.w * wv.w;
#pragma unroll
    for (int o = 16; o > 0; o >>= 1) d += __shfl_xor_sync(0xFFFFFFFFu, d, o);
    if (lane == 0) hw[node] = d;
}

// ---------------- layer 2 ----------------------------------------------------
__global__ void k_gather2(const int* __restrict__ start, const int* __restrict__ srow,
                          const float* __restrict__ snrm, const float* __restrict__ hw,
                          const float* __restrict__ dinv, const float* __restrict__ b2,
                          float* __restrict__ out, int N) {
    int node = blockIdx.x * blockDim.x + threadIdx.x;
    if (node >= N) return;
    float d = dinv[node];
    float sum = d * d * hw[node];
    int e  = start[node];
    int e1 = start[node + 1];
    for (; e + 1 < e1; e += 2) {
        sum += snrm[e] * hw[srow[e]] + snrm[e + 1] * hw[srow[e + 1]];
    }
    if (e < e1) sum += snrm[e] * hw[srow[e]];
    float v = sum + b2[0];
    out[node] = 1.0f / (1.0f + expf(-v));
}

// ---------------- launch ------------------------------------------------------
extern "C" void kernel_launch(void* const* d_in, const int* in_sizes, int n_in,
                              void* d_out, int out_size) {
    const float* x   = (const float*)d_in[0];
    const int*   ei  = (const int*)d_in[1];
    const float* ew  = (const float*)d_in[2];
    const float* W1  = (const float*)d_in[3];
    const float* b1  = (const float*)d_in[4];
    const float* W2  = (const float*)d_in[5];
    const float* b2  = (const float*)d_in[6];

    int N = in_sizes[0] / F;
    int E = in_sizes[2];
    const int* row = ei;
    const int* col = ei + E;

    float* out_pred = (float*)d_out;
    float* emb      = (float*)d_out + N;

    float* deg   = nullptr; cudaGetSymbolAddress((void**)&deg,   g_deg);
    float* dinv  = nullptr; cudaGetSymbolAddress((void**)&dinv,  g_dinv);
    float* xw    = nullptr; cudaGetSymbolAddress((void**)&xw,    g_xw);
    float* hw    = nullptr; cudaGetSymbolAddress((void**)&hw,    g_hw);
    int*   count = nullptr; cudaGetSymbolAddress((void**)&count, g_count);
    int*   start = nullptr; cudaGetSymbolAddress((void**)&start, g_start);
    int*   bsum  = nullptr; cudaGetSymbolAddress((void**)&bsum,  g_bsum);
    int*   srow  = nullptr; cudaGetSymbolAddress((void**)&srow,  g_srow);
    float* snrm  = nullptr; cudaGetSymbolAddress((void**)&snrm,  g_snrm);
    float* w1hi  = nullptr; cudaGetSymbolAddress((void**)&w1hi,  g_w1hi);
    float* w1lo  = nullptr; cudaGetSymbolAddress((void**)&w1lo,  g_w1lo);

    int nb = (N + CHUNK - 1) / CHUNK;

    static cudaStream_t s2 = nullptr;
    static cudaEvent_t ev_fork = nullptr, ev_join = nullptr;
    if (s2 == nullptr) {
        cudaStreamCreateWithFlags(&s2, cudaStreamNonBlocking);
        cudaEventCreateWithFlags(&ev_fork, cudaEventDisableTiming);
        cudaEventCreateWithFlags(&ev_join, cudaEventDisableTiming);
    }

    cudaEventRecord(ev_fork, 0);
    cudaStreamWaitEvent(s2, ev_fork, 0);

    // main stream: W split + tf32 tensor-core GEMM
    k_split_w<<<(F * F + 255) / 256, 256>>>(W1, w1hi, w1lo);
    k_gemm_tf32<<<(N + 127) / 128, 256>>>(x, w1hi, w1lo, xw, N);

    // s2: CSR build
    k_init<<<(N + 255) / 256, 256, 0, s2>>>(deg, count, N);
    k_edge_pass<<<(E + 255) / 256, 256, 0, s2>>>(col, ew, deg, count, E);
    k_dinv<<<(N + 255) / 256, 256, 0, s2>>>(deg, dinv, N);
    k_blocksum<<<nb, 256, 0, s2>>>(count, bsum, N);
    k_scan_bsum<<<1, 128, 0, s2>>>(bsum, start, nb, N, E);
    k_scan_scatter<<<nb, 256, 0, s2>>>(count, bsum, start, N);
    k_permute<<<(E + 255) / 256, 256, 0, s2>>>(row, col, ew, dinv, start, count, srow, snrm, E);

    cudaEventRecord(ev_join, s2);
    cudaStreamWaitEvent(0, ev_join, 0);

    k_gather1<<<(N + 7) / 8, 256>>>(start, srow, snrm, xw, dinv, b1, W2, emb, hw, N);
    k_gather2<<<(N + 255) / 256, 256>>>(start, srow, snrm, hw, dinv, b2, out_pred, N);
}

// round 5
// speedup vs baseline: 3.4347x; 1.1557x over previous
#include <cuda_runtime.h>
#include <cuda_fp16.h>
#include <math.h>
#include <stdint.h>

#define MAX_N 100000
#define MAX_E 1600000
#define F 128
#define CHUNK 1024
#define NB ((MAX_N + CHUNK - 1) / CHUNK)
#define WPAD 136   // smem row stride for W tiles (conflict-free fragment loads)

// ---------------- scratch (static device globals) ---------------------------
__device__ float g_deg[MAX_N];
__device__ float g_dinv[MAX_N];
__device__ __align__(16) __half g_xwh[MAX_N * F];   // x @ W1, fp16
__device__ float g_hw[MAX_N];
__device__ int   g_count[MAX_N];
__device__ int   g_start[MAX_N + 1];
__device__ int   g_bsum[NB + 1];
__device__ __align__(16) int2 g_edge[MAX_E];        // {src_row, norm-as-int}, CSR-sorted

// ---------------- init + degree + histogram ---------------------------------
__global__ void k_init(float* deg, int* count, int N) {
    int i = blockIdx.x * blockDim.x + threadIdx.x;
    if (i < N) { deg[i] = 1.0f; count[i] = 0; }
}

__global__ void k_edge_pass(const int* __restrict__ col, const float* __restrict__ ew,
                            float* deg, int* count, int E) {
    int e = blockIdx.x * blockDim.x + threadIdx.x;
    if (e < E) {
        int c = col[e];
        atomicAdd(&deg[c], ew[e]);
        atomicAdd(&count[c], 1);
    }
}

__global__ void k_dinv(const float* __restrict__ deg, float* dinv, int N) {
    int i = blockIdx.x * blockDim.x + threadIdx.x;
    if (i < N) {
        float d = deg[i];
        dinv[i] = (d > 0.0f) ? rsqrtf(d) : 0.0f;
    }
}

// ---------------- exclusive scan of count -> start --------------------------
__global__ void k_blocksum(const int* __restrict__ count, int* bsum, int N) {
    __shared__ int s[256];
    int base = blockIdx.x * CHUNK;
    int t = threadIdx.x;
    int local = 0;
#pragma unroll
    for (int j = 0; j < 4; j++) {
        int i = base + t * 4 + j;
        if (i < N) local += count[i];
    }
    s[t] = local;
    __syncthreads();
    for (int off = 128; off > 0; off >>= 1) {
        if (t < off) s[t] += s[t + off];
        __syncthreads();
    }
    if (t == 0) bsum[blockIdx.x] = s[0];
}

__global__ void k_scan_bsum(int* bsum, int* start, int nb, int N, int E) {
    __shared__ int s[128];
    int t = threadIdx.x;
    s[t] = (t < nb) ? bsum[t] : 0;
    __syncthreads();
    for (int off = 1; off < 128; off <<= 1) {
        int x = (t >= off) ? s[t - off] : 0;
        __syncthreads();
        s[t] += x;
        __syncthreads();
    }
    if (t < nb) bsum[t] = (t > 0) ? s[t - 1] : 0;
    if (t == 0) start[N] = E;
}

__global__ void k_scan_scatter(int* count, const int* __restrict__ bsum,
                               int* start, int N) {
    __shared__ int s[256];
    int base = blockIdx.x * CHUNK;
    int t = threadIdx.x;
    int v[4];
    int local = 0;
#pragma unroll
    for (int j = 0; j < 4; j++) {
        int i = base + t * 4 + j;
        v[j] = (i < N) ? count[i] : 0;
        local += v[j];
    }
    s[t] = local;
    __syncthreads();
    for (int off = 1; off < 256; off <<= 1) {
        int x = (t >= off) ? s[t - off] : 0;
        __syncthreads();
        s[t] += x;
        __syncthreads();
    }
    int excl = ((t > 0) ? s[t - 1] : 0) + bsum[blockIdx.x];
#pragma unroll
    for (int j = 0; j < 4; j++) {
        int i = base + t * 4 + j;
        if (i < N) {
            start[i] = excl;
            excl += v[j];
            count[i] = 0;
        }
    }
}

// ---------------- permute: sort (row, nrm) pairs by target -------------------
__global__ void k_permute(const int* __restrict__ row, const int* __restrict__ col,
                          const float* __restrict__ ew, const float* __restrict__ dinv,
                          const int* __restrict__ start, int* count,
                          int2* __restrict__ edge, int E) {
    int e = blockIdx.x * blockDim.x + threadIdx.x;
    if (e >= E) return;
    int c = col[e];
    int r = row[e];
    int pos = start[c] + atomicAdd(&count[c], 1);
    float nrm = dinv[r] * ew[e] * dinv[c];
    edge[pos] = make_int2(r, __float_as_int(nrm));
}

// ---------------- tf32 tensor-core GEMM: Y(fp16) = X @ W1 (3xTF32) -----------
__device__ __forceinline__ uint32_t f2tf32(float v) {
    uint32_t r;
    asm("cvt.rna.tf32.f32 %0, %1;" : "=r"(r) : "f"(v));
    return r;
}

// block 128x128, 8 warps (4 row-groups x 2 col-groups), warp = 32 rows x 64 cols
__global__ void __launch_bounds__(256, 2)
k_gemm_tf32(const float* __restrict__ X, const float* __restrict__ W1,
            __half* __restrict__ Y, int N) {
    __shared__ float Xs[2][128][8];
    __shared__ float Wh[2][8][WPAD];
    __shared__ float Wl[2][8][WPAD];

    int tid  = threadIdx.x;
    int lane = tid & 31;
    int wid  = tid >> 5;
    int wr   = wid >> 1;
    int wc   = wid & 1;
    int g    = lane >> 2;
    int tig  = lane & 3;
    int row0 = blockIdx.x * 128;

    int xrow = tid >> 1;
    int xoff = (tid & 1) * 4;
    int wkr  = tid >> 5;
    int wcc  = (tid & 31) * 4;

    float4 xv, wv;

    float acc[2][8][4];
#pragma unroll
    for (int rt = 0; rt < 2; rt++)
#pragma unroll
        for (int nt = 0; nt < 8; nt++)
#pragma unroll
            for (int j = 0; j < 4; j++) acc[rt][nt][j] = 0.0f;

    // stage W chunk with inline hi/lo split
    auto stageW = [&](int b, float4 w) {
        float h0 = __uint_as_float(f2tf32(w.x));
        float h1 = __uint_as_float(f2tf32(w.y));
        float h2 = __uint_as_float(f2tf32(w.z));
        float h3 = __uint_as_float(f2tf32(w.w));
        *(float4*)&Wh[b][wkr][wcc] = make_float4(h0, h1, h2, h3);
        *(float4*)&Wl[b][wkr][wcc] = make_float4(
            __uint_as_float(f2tf32(w.x - h0)), __uint_as_float(f2tf32(w.y - h1)),
            __uint_as_float(f2tf32(w.z - h2)), __uint_as_float(f2tf32(w.w - h3)));
    };

    {
        int gr = row0 + xrow;
        xv = (gr < N) ? *(const float4*)&X[(long)gr * F + xoff] : make_float4(0,0,0,0);
        wv = *(const float4*)&W1[wkr * F + wcc];
        *(float4*)&Xs[0][xrow][xoff] = xv;
        stageW(0, wv);
    }
    __syncthreads();

    int p = 0;
#pragma unroll
    for (int c = 0; c < 16; c++) {
        if (c < 15) {
            int k0 = (c + 1) * 8;
            int gr = row0 + xrow;
            xv = (gr < N) ? *(const float4*)&X[(long)gr * F + k0 + xoff] : make_float4(0,0,0,0);
            wv = *(const float4*)&W1[(k0 + wkr) * F + wcc];
        }

        uint32_t ah[2][4], al[2][4];
#pragma unroll
        for (int rt = 0; rt < 2; rt++) {
            int rb = wr * 32 + rt * 16;
            float a0 = Xs[p][rb + g][tig];
            float a1 = Xs[p][rb + g + 8][tig];
            float a2 = Xs[p][rb + g][tig + 4];
            float a3 = Xs[p][rb + g + 8][tig + 4];
            ah[rt][0] = f2tf32(a0); al[rt][0] = f2tf32(a0 - __uint_as_float(ah[rt][0]));
            ah[rt][1] = f2tf32(a1); al[rt][1] = f2tf32(a1 - __uint_as_float(ah[rt][1]));
            ah[rt][2] = f2tf32(a2); al[rt][2] = f2tf32(a2 - __uint_as_float(ah[rt][2]));
            ah[rt][3] = f2tf32(a3); al[rt][3] = f2tf32(a3 - __uint_as_float(ah[rt][3]));
        }

#pragma unroll
        for (int nt = 0; nt < 8; nt++) {
            int cb = wc * 64 + nt * 8;
            uint32_t bh0 = __float_as_uint(Wh[p][tig][cb + g]);
            uint32_t bh1 = __float_as_uint(Wh[p][tig + 4][cb + g]);
            uint32_t bl0 = __float_as_uint(Wl[p][tig][cb + g]);
            uint32_t bl1 = __float_as_uint(Wl[p][tig + 4][cb + g]);
#pragma unroll
            for (int rt = 0; rt < 2; rt++) {
                float* d = acc[rt][nt];
                asm volatile(
                    "mma.sync.aligned.m16n8k8.row.col.f32.tf32.tf32.f32 "
                    "{%0,%1,%2,%3}, {%4,%5,%6,%7}, {%8,%9}, {%0,%1,%2,%3};"
                    : "+f"(d[0]), "+f"(d[1]), "+f"(d[2]), "+f"(d[3])
                    : "r"(ah[rt][0]), "r"(ah[rt][1]), "r"(ah[rt][2]), "r"(ah[rt][3]),
                      "r"(bh0), "r"(bh1));
                asm volatile(
                    "mma.sync.aligned.m16n8k8.row.col.f32.tf32.tf32.f32 "
                    "{%0,%1,%2,%3}, {%4,%5,%6,%7}, {%8,%9}, {%0,%1,%2,%3};"
                    : "+f"(d[0]), "+f"(d[1]), "+f"(d[2]), "+f"(d[3])
                    : "r"(ah[rt][0]), "r"(ah[rt][1]), "r"(ah[rt][2]), "r"(ah[rt][3]),
                      "r"(bl0), "r"(bl1));
                asm volatile(
                    "mma.sync.aligned.m16n8k8.row.col.f32.tf32.tf32.f32 "
                    "{%0,%1,%2,%3}, {%4,%5,%6,%7}, {%8,%9}, {%0,%1,%2,%3};"
                    : "+f"(d[0]), "+f"(d[1]), "+f"(d[2]), "+f"(d[3])
                    : "r"(al[rt][0]), "r"(al[rt][1]), "r"(al[rt][2]), "r"(al[rt][3]),
                      "r"(bh0), "r"(bh1));
            }
        }

        if (c < 15) {
            int b = 1 - p;
            *(float4*)&Xs[b][xrow][xoff] = xv;
            stageW(b, wv);
            __syncthreads();
            p ^= 1;
        }
    }

    // epilogue: pack pairs to half2
#pragma unroll
    for (int rt = 0; rt < 2; rt++) {
        int r0g = row0 + wr * 32 + rt * 16 + g;
        int r1g = r0g + 8;
#pragma unroll
        for (int nt = 0; nt < 8; nt++) {
            int cc = wc * 64 + nt * 8 + 2 * tig;
            if (r0g < N)
                *(__half2*)&Y[(long)r0g * F + cc] = __floats2half2_rn(acc[rt][nt][0], acc[rt][nt][1]);
            if (r1g < N)
                *(__half2*)&Y[(long)r1g * F + cc] = __floats2half2_rn(acc[rt][nt][2], acc[rt][nt][3]);
        }
    }
}

// ---------------- layer 1 gather (CSR, fp16 messages) + fused h@W2 ----------
__device__ __forceinline__ void acc_row(float4& acc, const __half* base, int lane, float n) {
    uint2 u = ((const uint2*)base)[lane];
    float2 f01 = __half22float2(*reinterpret_cast<__half2*>(&u.x));
    float2 f23 = __half22float2(*reinterpret_cast<__half2*>(&u.y));
    acc.x += n * f01.x; acc.y += n * f01.y;
    acc.z += n * f23.x; acc.w += n * f23.y;
}

__global__ void k_gather1(const int* __restrict__ start, const int2* __restrict__ edge,
                          const __half* __restrict__ xwh,
                          const float* __restrict__ dinv, const float* __restrict__ b1,
                          const float* __restrict__ W2,
                          float* __restrict__ emb, float* __restrict__ hw, int N) {
    int node = blockIdx.x * (blockDim.x >> 5) + (threadIdx.x >> 5);
    if (node >= N) return;
    int lane = threadIdx.x & 31;

    float s = dinv[node]; s = s * s;
    float4 acc = make_float4(0.f, 0.f, 0.f, 0.f);
    acc_row(acc, &xwh[(long)node * F], lane, s);

    int e  = start[node];
    int e1 = start[node + 1];
    for (; e + 3 < e1; e += 4) {
        int2 p0 = edge[e],   p1 = edge[e+1], p2 = edge[e+2], p3 = edge[e+3];
        acc_row(acc, &xwh[(long)p0.x * F], lane, __int_as_float(p0.y));
        acc_row(acc, &xwh[(long)p1.x * F], lane, __int_as_float(p1.y));
        acc_row(acc, &xwh[(long)p2.x * F], lane, __int_as_float(p2.y));
        acc_row(acc, &xwh[(long)p3.x * F], lane, __int_as_float(p3.y));
    }
    for (; e < e1; e++) {
        int2 p0 = edge[e];
        acc_row(acc, &xwh[(long)p0.x * F], lane, __int_as_float(p0.y));
    }

    float4 b = ((const float4*)b1)[lane];
    acc.x += b.x; acc.y += b.y; acc.z += b.z; acc.w += b.w;
    acc.x = (acc.x > 0.f) ? acc.x : expm1f(acc.x);
    acc.y = (acc.y > 0.f) ? acc.y : expm1f(acc.y);
    acc.z = (acc.z > 0.f) ? acc.z : expm1f(acc.z);
    acc.w = (acc.w > 0.f) ? acc.w : expm1f(acc.w);
    ((float4*)&emb[(long)node * F])[lane] = acc;

    float4 wv = ((const float4*)W2)[lane];
    float d = acc.x * wv.x + acc.y * wv.y + acc.z * wv.z + acc.w * wv.w;
#pragma unroll
    for (int o = 16; o > 0; o >>= 1) d += __shfl_xor_sync(0xFFFFFFFFu, d, o);
    if (lane == 0) hw[node] = d;
}

// ---------------- layer 2 ----------------------------------------------------
__global__ void k_gather2(const int* __restrict__ start, const int2* __restrict__ edge,
                          const float* __restrict__ hw,
                          const float* __restrict__ dinv, const float* __restrict__ b2,
                          float* __restrict__ out, int N) {
    int node = blockIdx.x * blockDim.x + threadIdx.x;
    if (node >= N) return;
    float d = dinv[node];
    float sum = d * d * hw[node];
    int e  = start[node];
    int e1 = start[node + 1];
    for (; e + 1 < e1; e += 2) {
        int2 p0 = edge[e], p1 = edge[e + 1];
        sum += __int_as_float(p0.y) * hw[p0.x] + __int_as_float(p1.y) * hw[p1.x];
    }
    if (e < e1) {
        int2 p0 = edge[e];
        sum += __int_as_float(p0.y) * hw[p0.x];
    }
    float v = sum + b2[0];
    out[node] = 1.0f / (1.0f + expf(-v));
}

// ---------------- launch ------------------------------------------------------
extern "C" void kernel_launch(void* const* d_in, const int* in_sizes, int n_in,
                              void* d_out, int out_size) {
    const float* x   = (const float*)d_in[0];
    const int*   ei  = (const int*)d_in[1];
    const float* ew  = (const float*)d_in[2];
    const float* W1  = (const float*)d_in[3];
    const float* b1  = (const float*)d_in[4];
    const float* W2  = (const float*)d_in[5];
    const float* b2  = (const float*)d_in[6];

    int N = in_sizes[0] / F;
    int E = in_sizes[2];
    const int* row = ei;
    const int* col = ei + E;

    float* out_pred = (float*)d_out;
    float* emb      = (float*)d_out + N;

    float*  deg   = nullptr; cudaGetSymbolAddress((void**)&deg,   g_deg);
    float*  dinv  = nullptr; cudaGetSymbolAddress((void**)&dinv,  g_dinv);
    __half* xwh   = nullptr; cudaGetSymbolAddress((void**)&xwh,   g_xwh);
    float*  hw    = nullptr; cudaGetSymbolAddress((void**)&hw,    g_hw);
    int*    count = nullptr; cudaGetSymbolAddress((void**)&count, g_count);
    int*    start = nullptr; cudaGetSymbolAddress((void**)&start, g_start);
    int*    bsum  = nullptr; cudaGetSymbolAddress((void**)&bsum,  g_bsum);
    int2*   edge  = nullptr; cudaGetSymbolAddress((void**)&edge,  g_edge);

    int nb = (N + CHUNK - 1) / CHUNK;

    static cudaStream_t s2 = nullptr;
    static cudaEvent_t ev_fork = nullptr, ev_join = nullptr;
    if (s2 == nullptr) {
        cudaStreamCreateWithFlags(&s2, cudaStreamNonBlocking);
        cudaEventCreateWithFlags(&ev_fork, cudaEventDisableTiming);
        cudaEventCreateWithFlags(&ev_join, cudaEventDisableTiming);
    }

    cudaEventRecord(ev_fork, 0);
    cudaStreamWaitEvent(s2, ev_fork, 0);

    // main stream: tf32 tensor-core GEMM (inline W split, fp16 output)
    k_gemm_tf32<<<(N + 127) / 128, 256>>>(x, W1, xwh, N);

    // s2: CSR build
    k_init<<<(N + 255) / 256, 256, 0, s2>>>(deg, count, N);
    k_edge_pass<<<(E + 255) / 256, 256, 0, s2>>>(col, ew, deg, count, E);
    k_dinv<<<(N + 255) / 256, 256, 0, s2>>>(deg, dinv, N);
    k_blocksum<<<nb, 256, 0, s2>>>(count, bsum, N);
    k_scan_bsum<<<1, 128, 0, s2>>>(bsum, start, nb, N, E);
    k_scan_scatter<<<nb, 256, 0, s2>>>(count, bsum, start, N);
    k_permute<<<(E + 255) / 256, 256, 0, s2>>>(row, col, ew, dinv, start, count, edge, E);

    cudaEventRecord(ev_join, s2);
    cudaStreamWaitEvent(0, ev_join, 0);

    k_gather1<<<(N + 7) / 8, 256>>>(start, edge, xwh, dinv, b1, W2, emb, hw, N);
    k_gather2<<<(N + 255) / 256, 256>>>(start, edge, hw, dinv, b2, out_pred, N);
}

// round 6
// speedup vs baseline: 3.5734x; 1.0404x over previous
#include <cuda_runtime.h>
#include <cuda_fp16.h>
#include <math.h>
#include <stdint.h>

#define MAX_N 100000
#define MAX_E 1600000
#define F 128
#define CHUNK 1024
#define NB ((MAX_N + CHUNK - 1) / CHUNK)
#define WPAD 136   // smem row stride for W tiles (conflict-free fragment loads)

// ---------------- scratch (static device globals) ---------------------------
__device__ float g_deg[MAX_N];
__device__ float g_dinv[MAX_N];
__device__ __align__(16) __half g_xwh[MAX_N * F];   // x @ W1, fp16
__device__ float g_hw[MAX_N];
__device__ int   g_count[MAX_N];
__device__ int   g_start[MAX_N + 1];
__device__ int   g_bsum[NB + 1];
__device__ int   g_rank[MAX_E];                     // within-target rank of each edge
__device__ __align__(16) int2 g_edge[MAX_E];        // {src_row, norm-as-int}, CSR-sorted

// ---------------- init + degree + histogram ---------------------------------
__global__ void k_init(float* deg, int* count, int N) {
    int i = blockIdx.x * blockDim.x + threadIdx.x;
    if (i < N) { deg[i] = 1.0f; count[i] = 0; }
}

// one pass: weighted degree + count histogram; atomic return value IS the rank
__global__ void k_edge_pass(const int* __restrict__ col, const float* __restrict__ ew,
                            float* deg, int* count, int* __restrict__ rank, int E) {
    int e = blockIdx.x * blockDim.x + threadIdx.x;
    if (e < E) {
        int c = col[e];
        atomicAdd(&deg[c], ew[e]);
        rank[e] = atomicAdd(&count[c], 1);
    }
}

// fused: dinv computation + per-chunk block sums of count
__global__ void k_dinv_blocksum(const float* __restrict__ deg, float* __restrict__ dinv,
                                const int* __restrict__ count, int* bsum, int N) {
    __shared__ int s[256];
    int base = blockIdx.x * CHUNK;
    int t = threadIdx.x;
    int local = 0;
#pragma unroll
    for (int j = 0; j < 4; j++) {
        int i = base + t * 4 + j;
        if (i < N) {
            local += count[i];
            float d = deg[i];
            dinv[i] = (d > 0.0f) ? rsqrtf(d) : 0.0f;
        }
    }
    s[t] = local;
    __syncthreads();
    for (int off = 128; off > 0; off >>= 1) {
        if (t < off) s[t] += s[t + off];
        __syncthreads();
    }
    if (t == 0) bsum[blockIdx.x] = s[0];
}

__global__ void k_scan_bsum(int* bsum, int* start, int nb, int N, int E) {
    __shared__ int s[128];
    int t = threadIdx.x;
    s[t] = (t < nb) ? bsum[t] : 0;
    __syncthreads();
    for (int off = 1; off < 128; off <<= 1) {
        int x = (t >= off) ? s[t - off] : 0;
        __syncthreads();
        s[t] += x;
        __syncthreads();
    }
    if (t < nb) bsum[t] = (t > 0) ? s[t - 1] : 0;
    if (t == 0) start[N] = E;
}

__global__ void k_scan_scatter(const int* __restrict__ count, const int* __restrict__ bsum,
                               int* start, int N) {
    __shared__ int s[256];
    int base = blockIdx.x * CHUNK;
    int t = threadIdx.x;
    int v[4];
    int local = 0;
#pragma unroll
    for (int j = 0; j < 4; j++) {
        int i = base + t * 4 + j;
        v[j] = (i < N) ? count[i] : 0;
        local += v[j];
    }
    s[t] = local;
    __syncthreads();
    for (int off = 1; off < 256; off <<= 1) {
        int x = (t >= off) ? s[t - off] : 0;
        __syncthreads();
        s[t] += x;
        __syncthreads();
    }
    int excl = ((t > 0) ? s[t - 1] : 0) + bsum[blockIdx.x];
#pragma unroll
    for (int j = 0; j < 4; j++) {
        int i = base + t * 4 + j;
        if (i < N) {
            start[i] = excl;
            excl += v[j];
        }
    }
}

// ---------------- permute (atomic-free): pos = start[col] + rank -------------
__global__ void k_permute(const int* __restrict__ row, const int* __restrict__ col,
                          const float* __restrict__ ew, const float* __restrict__ dinv,
                          const int* __restrict__ start, const int* __restrict__ rank,
                          int2* __restrict__ edge, int E) {
    int e = blockIdx.x * blockDim.x + threadIdx.x;
    if (e >= E) return;
    int c = col[e];
    int r = row[e];
    int pos = start[c] + rank[e];
    float nrm = dinv[r] * ew[e] * dinv[c];
    edge[pos] = make_int2(r, __float_as_int(nrm));
}

// ---------------- tf32 tensor-core GEMM: Y(fp16) = X @ W1 (3xTF32) -----------
__device__ __forceinline__ uint32_t f2tf32(float v) {
    uint32_t r;
    asm("cvt.rna.tf32.f32 %0, %1;" : "=r"(r) : "f"(v));
    return r;
}

// block 128x128, 8 warps (4 row-groups x 2 col-groups), warp = 32 rows x 64 cols
__global__ void __launch_bounds__(256, 2)
k_gemm_tf32(const float* __restrict__ X, const float* __restrict__ W1,
            __half* __restrict__ Y, int N) {
    __shared__ float Xs[2][128][8];
    __shared__ float Wh[2][8][WPAD];
    __shared__ float Wl[2][8][WPAD];

    int tid  = threadIdx.x;
    int lane = tid & 31;
    int wid  = tid >> 5;
    int wr   = wid >> 1;
    int wc   = wid & 1;
    int g    = lane >> 2;
    int tig  = lane & 3;
    int row0 = blockIdx.x * 128;

    int xrow = tid >> 1;
    int xoff = (tid & 1) * 4;
    int wkr  = tid >> 5;
    int wcc  = (tid & 31) * 4;

    float4 xv, wv;

    float acc[2][8][4];
#pragma unroll
    for (int rt = 0; rt < 2; rt++)
#pragma unroll
        for (int nt = 0; nt < 8; nt++)
#pragma unroll
            for (int j = 0; j < 4; j++) acc[rt][nt][j] = 0.0f;

    auto stageW = [&](int b, float4 w) {
        float h0 = __uint_as_float(f2tf32(w.x));
        float h1 = __uint_as_float(f2tf32(w.y));
        float h2 = __uint_as_float(f2tf32(w.z));
        float h3 = __uint_as_float(f2tf32(w.w));
        *(float4*)&Wh[b][wkr][wcc] = make_float4(h0, h1, h2, h3);
        *(float4*)&Wl[b][wkr][wcc] = make_float4(
            __uint_as_float(f2tf32(w.x - h0)), __uint_as_float(f2tf32(w.y - h1)),
            __uint_as_float(f2tf32(w.z - h2)), __uint_as_float(f2tf32(w.w - h3)));
    };

    {
        int gr = row0 + xrow;
        xv = (gr < N) ? *(const float4*)&X[(long)gr * F + xoff] : make_float4(0,0,0,0);
        wv = *(const float4*)&W1[wkr * F + wcc];
        *(float4*)&Xs[0][xrow][xoff] = xv;
        stageW(0, wv);
    }
    __syncthreads();

    int p = 0;
#pragma unroll
    for (int c = 0; c < 16; c++) {
        if (c < 15) {
            int k0 = (c + 1) * 8;
            int gr = row0 + xrow;
            xv = (gr < N) ? *(const float4*)&X[(long)gr * F + k0 + xoff] : make_float4(0,0,0,0);
            wv = *(const float4*)&W1[(k0 + wkr) * F + wcc];
        }

        uint32_t ah[2][4], al[2][4];
#pragma unroll
        for (int rt = 0; rt < 2; rt++) {
            int rb = wr * 32 + rt * 16;
            float a0 = Xs[p][rb + g][tig];
            float a1 = Xs[p][rb + g + 8][tig];
            float a2 = Xs[p][rb + g][tig + 4];
            float a3 = Xs[p][rb + g + 8][tig + 4];
            ah[rt][0] = f2tf32(a0); al[rt][0] = f2tf32(a0 - __uint_as_float(ah[rt][0]));
            ah[rt][1] = f2tf32(a1); al[rt][1] = f2tf32(a1 - __uint_as_float(ah[rt][1]));
            ah[rt][2] = f2tf32(a2); al[rt][2] = f2tf32(a2 - __uint_as_float(ah[rt][2]));
            ah[rt][3] = f2tf32(a3); al[rt][3] = f2tf32(a3 - __uint_as_float(ah[rt][3]));
        }

#pragma unroll
        for (int nt = 0; nt < 8; nt++) {
            int cb = wc * 64 + nt * 8;
            uint32_t bh0 = __float_as_uint(Wh[p][tig][cb + g]);
            uint32_t bh1 = __float_as_uint(Wh[p][tig + 4][cb + g]);
            uint32_t bl0 = __float_as_uint(Wl[p][tig][cb + g]);
            uint32_t bl1 = __float_as_uint(Wl[p][tig + 4][cb + g]);
#pragma unroll
            for (int rt = 0; rt < 2; rt++) {
                float* d = acc[rt][nt];
                asm volatile(
                    "mma.sync.aligned.m16n8k8.row.col.f32.tf32.tf32.f32 "
                    "{%0,%1,%2,%3}, {%4,%5,%6,%7}, {%8,%9}, {%0,%1,%2,%3};"
                    : "+f"(d[0]), "+f"(d[1]), "+f"(d[2]), "+f"(d[3])
                    : "r"(ah[rt][0]), "r"(ah[rt][1]), "r"(ah[rt][2]), "r"(ah[rt][3]),
                      "r"(bh0), "r"(bh1));
                asm volatile(
                    "mma.sync.aligned.m16n8k8.row.col.f32.tf32.tf32.f32 "
                    "{%0,%1,%2,%3}, {%4,%5,%6,%7}, {%8,%9}, {%0,%1,%2,%3};"
                    : "+f"(d[0]), "+f"(d[1]), "+f"(d[2]), "+f"(d[3])
                    : "r"(ah[rt][0]), "r"(ah[rt][1]), "r"(ah[rt][2]), "r"(ah[rt][3]),
                      "r"(bl0), "r"(bl1));
                asm volatile(
                    "mma.sync.aligned.m16n8k8.row.col.f32.tf32.tf32.f32 "
                    "{%0,%1,%2,%3}, {%4,%5,%6,%7}, {%8,%9}, {%0,%1,%2,%3};"
                    : "+f"(d[0]), "+f"(d[1]), "+f"(d[2]), "+f"(d[3])
                    : "r"(al[rt][0]), "r"(al[rt][1]), "r"(al[rt][2]), "r"(al[rt][3]),
                      "r"(bh0), "r"(bh1));
            }
        }

        if (c < 15) {
            int b = 1 - p;
            *(float4*)&Xs[b][xrow][xoff] = xv;
            stageW(b, wv);
            __syncthreads();
            p ^= 1;
        }
    }

#pragma unroll
    for (int rt = 0; rt < 2; rt++) {
        int r0g = row0 + wr * 32 + rt * 16 + g;
        int r1g = r0g + 8;
#pragma unroll
        for (int nt = 0; nt < 8; nt++) {
            int cc = wc * 64 + nt * 8 + 2 * tig;
            if (r0g < N)
                *(__half2*)&Y[(long)r0g * F + cc] = __floats2half2_rn(acc[rt][nt][0], acc[rt][nt][1]);
            if (r1g < N)
                *(__half2*)&Y[(long)r1g * F + cc] = __floats2half2_rn(acc[rt][nt][2], acc[rt][nt][3]);
        }
    }
}

// ---------------- layer 1 gather (CSR, fp16 messages) + fused h@W2 ----------
__device__ __forceinline__ void acc_row(float4& acc, const __half* base, int lane, float n) {
    uint2 u = ((const uint2*)base)[lane];
    float2 f01 = __half22float2(*reinterpret_cast<__half2*>(&u.x));
    float2 f23 = __half22float2(*reinterpret_cast<__half2*>(&u.y));
    acc.x += n * f01.x; acc.y += n * f01.y;
    acc.z += n * f23.x; acc.w += n * f23.y;
}

__global__ void k_gather1(const int* __restrict__ start, const int2* __restrict__ edge,
                          const __half* __restrict__ xwh,
                          const float* __restrict__ dinv, const float* __restrict__ b1,
                          const float* __restrict__ W2,
                          float* __restrict__ emb, float* __restrict__ hw, int N) {
    int node = blockIdx.x * (blockDim.x >> 5) + (threadIdx.x >> 5);
    if (node >= N) return;
    int lane = threadIdx.x & 31;

    float s = dinv[node]; s = s * s;
    float4 acc = make_float4(0.f, 0.f, 0.f, 0.f);
    acc_row(acc, &xwh[(long)node * F], lane, s);

    int e  = start[node];
    int e1 = start[node + 1];
    for (; e + 3 < e1; e += 4) {
        int2 p0 = edge[e],   p1 = edge[e+1], p2 = edge[e+2], p3 = edge[e+3];
        acc_row(acc, &xwh[(long)p0.x * F], lane, __int_as_float(p0.y));
        acc_row(acc, &xwh[(long)p1.x * F], lane, __int_as_float(p1.y));
        acc_row(acc, &xwh[(long)p2.x * F], lane, __int_as_float(p2.y));
        acc_row(acc, &xwh[(long)p3.x * F], lane, __int_as_float(p3.y));
    }
    for (; e < e1; e++) {
        int2 p0 = edge[e];
        acc_row(acc, &xwh[(long)p0.x * F], lane, __int_as_float(p0.y));
    }

    float4 b = ((const float4*)b1)[lane];
    acc.x += b.x; acc.y += b.y; acc.z += b.z; acc.w += b.w;
    acc.x = (acc.x > 0.f) ? acc.x : expm1f(acc.x);
    acc.y = (acc.y > 0.f) ? acc.y : expm1f(acc.y);
    acc.z = (acc.z > 0.f) ? acc.z : expm1f(acc.z);
    acc.w = (acc.w > 0.f) ? acc.w : expm1f(acc.w);
    ((float4*)&emb[(long)node * F])[lane] = acc;

    float4 wv = ((const float4*)W2)[lane];
    float d = acc.x * wv.x + acc.y * wv.y + acc.z * wv.z + acc.w * wv.w;
#pragma unroll
    for (int o = 16; o > 0; o >>= 1) d += __shfl_xor_sync(0xFFFFFFFFu, d, o);
    if (lane == 0) hw[node] = d;
}

// ---------------- layer 2 ----------------------------------------------------
__global__ void k_gather2(const int* __restrict__ start, const int2* __restrict__ edge,
                          const float* __restrict__ hw,
                          const float* __restrict__ dinv, const float* __restrict__ b2,
                          float* __restrict__ out, int N) {
    int node = blockIdx.x * blockDim.x + threadIdx.x;
    if (node >= N) return;
    float d = dinv[node];
    float sum = d * d * hw[node];
    int e  = start[node];
    int e1 = start[node + 1];
    for (; e + 1 < e1; e += 2) {
        int2 p0 = edge[e], p1 = edge[e + 1];
        sum += __int_as_float(p0.y) * hw[p0.x] + __int_as_float(p1.y) * hw[p1.x];
    }
    if (e < e1) {
        int2 p0 = edge[e];
        sum += __int_as_float(p0.y) * hw[p0.x];
    }
    float v = sum + b2[0];
    out[node] = 1.0f / (1.0f + expf(-v));
}

// ---------------- launch ------------------------------------------------------
extern "C" void kernel_launch(void* const* d_in, const int* in_sizes, int n_in,
                              void* d_out, int out_size) {
    const float* x   = (const float*)d_in[0];
    const int*   ei  = (const int*)d_in[1];
    const float* ew  = (const float*)d_in[2];
    const float* W1  = (const float*)d_in[3];
    const float* b1  = (const float*)d_in[4];
    const float* W2  = (const float*)d_in[5];
    const float* b2  = (const float*)d_in[6];

    int N = in_sizes[0] / F;
    int E = in_sizes[2];
    const int* row = ei;
    const int* col = ei + E;

    float* out_pred = (float*)d_out;
    float* emb      = (float*)d_out + N;

    float*  deg   = nullptr; cudaGetSymbolAddress((void**)&deg,   g_deg);
    float*  dinv  = nullptr; cudaGetSymbolAddress((void**)&dinv,  g_dinv);
    __half* xwh   = nullptr; cudaGetSymbolAddress((void**)&xwh,   g_xwh);
    float*  hw    = nullptr; cudaGetSymbolAddress((void**)&hw,    g_hw);
    int*    count = nullptr; cudaGetSymbolAddress((void**)&count, g_count);
    int*    start = nullptr; cudaGetSymbolAddress((void**)&start, g_start);
    int*    bsum  = nullptr; cudaGetSymbolAddress((void**)&bsum,  g_bsum);
    int*    rank  = nullptr; cudaGetSymbolAddress((void**)&rank,  g_rank);
    int2*   edge  = nullptr; cudaGetSymbolAddress((void**)&edge,  g_edge);

    int nb = (N + CHUNK - 1) / CHUNK;

    static cudaStream_t s2 = nullptr;
    static cudaEvent_t ev_fork = nullptr, ev_join = nullptr;
    if (s2 == nullptr) {
        cudaStreamCreateWithFlags(&s2, cudaStreamNonBlocking);
        cudaEventCreateWithFlags(&ev_fork, cudaEventDisableTiming);
        cudaEventCreateWithFlags(&ev_join, cudaEventDisableTiming);
    }

    cudaEventRecord(ev_fork, 0);
    cudaStreamWaitEvent(s2, ev_fork, 0);

    // main stream: tf32 tensor-core GEMM (inline W split, fp16 output)
    k_gemm_tf32<<<(N + 127) / 128, 256>>>(x, W1, xwh, N);

    // s2: CSR build (atomic-free permute via rank trick)
    k_init<<<(N + 255) / 256, 256, 0, s2>>>(deg, count, N);
    k_edge_pass<<<(E + 255) / 256, 256, 0, s2>>>(col, ew, deg, count, rank, E);
    k_dinv_blocksum<<<nb, 256, 0, s2>>>(deg, dinv, count, bsum, N);
    k_scan_bsum<<<1, 128, 0, s2>>>(bsum, start, nb, N, E);
    k_scan_scatter<<<nb, 256, 0, s2>>>(count, bsum, start, N);
    k_permute<<<(E + 255) / 256, 256, 0, s2>>>(row, col, ew, dinv, start, rank, edge, E);

    cudaEventRecord(ev_join, s2);
    cudaStreamWaitEvent(0, ev_join, 0);

    k_gather1<<<(N + 7) / 8, 256>>>(start, edge, xwh, dinv, b1, W2, emb, hw, N);
    k_gather2<<<(N + 255) / 256, 256>>>(start, edge, hw, dinv, b2, out_pred, N);
}

// round 7
// speedup vs baseline: 3.7350x; 1.0452x over previous
#include <cuda_runtime.h>
#include <cuda_fp16.h>
#include <math.h>
#include <stdint.h>

#define MAX_N 100000
#define MAX_E 1600000
#define F 128
#define CHUNK 1024
#define NB ((MAX_N + CHUNK - 1) / CHUNK)
#define WPAD 136          // smem row stride for W tiles (conflict-free fragment loads)
#define DEG_SCALE 33554432.0f   // 2^25 fixed-point for weighted degree

// ---------------- scratch (static device globals) ---------------------------
__device__ unsigned long long g_packed[MAX_N];      // hi: count, lo: deg fixed-point
__device__ float g_dinv[MAX_N];
__device__ __align__(16) __half g_xwh[MAX_N * F];   // x @ W1, fp16
__device__ float g_hw[MAX_N];
__device__ int   g_start[MAX_N + 1];
__device__ int   g_bsum[NB + 1];
__device__ int   g_rank[MAX_E];                     // within-target rank of each edge
__device__ __align__(16) int2 g_edge[MAX_E];        // {src_row, norm-as-int}, CSR-sorted

// ---------------- edge pass: ONE packed atomic per edge ----------------------
__global__ void k_edge_pass(const int* __restrict__ col, const float* __restrict__ ew,
                            unsigned long long* packed, int* __restrict__ rank, int E) {
    int e = blockIdx.x * blockDim.x + threadIdx.x;
    if (e < E) {
        int c = col[e];
        unsigned int q = __float2uint_rn(ew[e] * DEG_SCALE);
        unsigned long long old =
            atomicAdd(&packed[c], (1ULL << 32) | (unsigned long long)q);
        rank[e] = (int)(old >> 32);
    }
}

// fused: dinv (with +1 self-loop) + per-chunk block sums of counts
__global__ void k_dinv_blocksum(const unsigned long long* __restrict__ packed,
                                float* __restrict__ dinv, int* bsum, int N) {
    __shared__ int s[256];
    int base = blockIdx.x * CHUNK;
    int t = threadIdx.x;
    int local = 0;
#pragma unroll
    for (int j = 0; j < 4; j++) {
        int i = base + t * 4 + j;
        if (i < N) {
            unsigned long long p = packed[i];
            local += (int)(p >> 32);
            float d = 1.0f + (float)(unsigned int)(p & 0xFFFFFFFFu) * (1.0f / DEG_SCALE);
            dinv[i] = rsqrtf(d);
        }
    }
    s[t] = local;
    __syncthreads();
    for (int off = 128; off > 0; off >>= 1) {
        if (t < off) s[t] += s[t + off];
        __syncthreads();
    }
    if (t == 0) bsum[blockIdx.x] = s[0];
}

__global__ void k_scan_bsum(int* bsum, int* start, int nb, int N, int E) {
    __shared__ int s[128];
    int t = threadIdx.x;
    s[t] = (t < nb) ? bsum[t] : 0;
    __syncthreads();
    for (int off = 1; off < 128; off <<= 1) {
        int x = (t >= off) ? s[t - off] : 0;
        __syncthreads();
        s[t] += x;
        __syncthreads();
    }
    if (t < nb) bsum[t] = (t > 0) ? s[t - 1] : 0;
    if (t == 0) start[N] = E;
}

__global__ void k_scan_scatter(const unsigned long long* __restrict__ packed,
                               const int* __restrict__ bsum, int* start, int N) {
    __shared__ int s[256];
    int base = blockIdx.x * CHUNK;
    int t = threadIdx.x;
    int v[4];
    int local = 0;
#pragma unroll
    for (int j = 0; j < 4; j++) {
        int i = base + t * 4 + j;
        v[j] = (i < N) ? (int)(packed[i] >> 32) : 0;
        local += v[j];
    }
    s[t] = local;
    __syncthreads();
    for (int off = 1; off < 256; off <<= 1) {
        int x = (t >= off) ? s[t - off] : 0;
        __syncthreads();
        s[t] += x;
        __syncthreads();
    }
    int excl = ((t > 0) ? s[t - 1] : 0) + bsum[blockIdx.x];
#pragma unroll
    for (int j = 0; j < 4; j++) {
        int i = base + t * 4 + j;
        if (i < N) {
            start[i] = excl;
            excl += v[j];
        }
    }
}

// ---------------- permute (atomic-free): pos = start[col] + rank -------------
__global__ void k_permute(const int* __restrict__ row, const int* __restrict__ col,
                          const float* __restrict__ ew, const float* __restrict__ dinv,
                          const int* __restrict__ start, const int* __restrict__ rank,
                          int2* __restrict__ edge, int E) {
    int e = blockIdx.x * blockDim.x + threadIdx.x;
    if (e >= E) return;
    int c = col[e];
    int r = row[e];
    int pos = start[c] + rank[e];
    float nrm = dinv[r] * ew[e] * dinv[c];
    edge[pos] = make_int2(r, __float_as_int(nrm));
}

// ---------------- tf32 tensor-core GEMM: Y(fp16) = X @ W1 (3xTF32) -----------
__device__ __forceinline__ uint32_t f2tf32(float v) {
    uint32_t r;
    asm("cvt.rna.tf32.f32 %0, %1;" : "=r"(r) : "f"(v));
    return r;
}

// block 128x128, 8 warps (4 row-groups x 2 col-groups), warp = 32 rows x 64 cols
__global__ void __launch_bounds__(256, 2)
k_gemm_tf32(const float* __restrict__ X, const float* __restrict__ W1,
            __half* __restrict__ Y, int N) {
    __shared__ float Xs[2][128][8];
    __shared__ float Wh[2][8][WPAD];
    __shared__ float Wl[2][8][WPAD];

    int tid  = threadIdx.x;
    int lane = tid & 31;
    int wid  = tid >> 5;
    int wr   = wid >> 1;
    int wc   = wid & 1;
    int g    = lane >> 2;
    int tig  = lane & 3;
    int row0 = blockIdx.x * 128;

    int xrow = tid >> 1;
    int xoff = (tid & 1) * 4;
    int wkr  = tid >> 5;
    int wcc  = (tid & 31) * 4;

    float4 xv, wv;

    float acc[2][8][4];
#pragma unroll
    for (int rt = 0; rt < 2; rt++)
#pragma unroll
        for (int nt = 0; nt < 8; nt++)
#pragma unroll
            for (int j = 0; j < 4; j++) acc[rt][nt][j] = 0.0f;

    auto stageW = [&](int b, float4 w) {
        float h0 = __uint_as_float(f2tf32(w.x));
        float h1 = __uint_as_float(f2tf32(w.y));
        float h2 = __uint_as_float(f2tf32(w.z));
        float h3 = __uint_as_float(f2tf32(w.w));
        *(float4*)&Wh[b][wkr][wcc] = make_float4(h0, h1, h2, h3);
        *(float4*)&Wl[b][wkr][wcc] = make_float4(
            __uint_as_float(f2tf32(w.x - h0)), __uint_as_float(f2tf32(w.y - h1)),
            __uint_as_float(f2tf32(w.z - h2)), __uint_as_float(f2tf32(w.w - h3)));
    };

    {
        int gr = row0 + xrow;
        xv = (gr < N) ? __ldcs((const float4*)&X[(long)gr * F + xoff]) : make_float4(0,0,0,0);
        wv = *(const float4*)&W1[wkr * F + wcc];
        *(float4*)&Xs[0][xrow][xoff] = xv;
        stageW(0, wv);
    }
    __syncthreads();

    int p = 0;
#pragma unroll
    for (int c = 0; c < 16; c++) {
        if (c < 15) {
            int k0 = (c + 1) * 8;
            int gr = row0 + xrow;
            xv = (gr < N) ? __ldcs((const float4*)&X[(long)gr * F + k0 + xoff]) : make_float4(0,0,0,0);
            wv = *(const float4*)&W1[(k0 + wkr) * F + wcc];
        }

        uint32_t ah[2][4], al[2][4];
#pragma unroll
        for (int rt = 0; rt < 2; rt++) {
            int rb = wr * 32 + rt * 16;
            float a0 = Xs[p][rb + g][tig];
            float a1 = Xs[p][rb + g + 8][tig];
            float a2 = Xs[p][rb + g][tig + 4];
            float a3 = Xs[p][rb + g + 8][tig + 4];
            ah[rt][0] = f2tf32(a0); al[rt][0] = f2tf32(a0 - __uint_as_float(ah[rt][0]));
            ah[rt][1] = f2tf32(a1); al[rt][1] = f2tf32(a1 - __uint_as_float(ah[rt][1]));
            ah[rt][2] = f2tf32(a2); al[rt][2] = f2tf32(a2 - __uint_as_float(ah[rt][2]));
            ah[rt][3] = f2tf32(a3); al[rt][3] = f2tf32(a3 - __uint_as_float(ah[rt][3]));
        }

#pragma unroll
        for (int nt = 0; nt < 8; nt++) {
            int cb = wc * 64 + nt * 8;
            uint32_t bh0 = __float_as_uint(Wh[p][tig][cb + g]);
            uint32_t bh1 = __float_as_uint(Wh[p][tig + 4][cb + g]);
            uint32_t bl0 = __float_as_uint(Wl[p][tig][cb + g]);
            uint32_t bl1 = __float_as_uint(Wl[p][tig + 4][cb + g]);
#pragma unroll
            for (int rt = 0; rt < 2; rt++) {
                float* d = acc[rt][nt];
                asm volatile(
                    "mma.sync.aligned.m16n8k8.row.col.f32.tf32.tf32.f32 "
                    "{%0,%1,%2,%3}, {%4,%5,%6,%7}, {%8,%9}, {%0,%1,%2,%3};"
                    : "+f"(d[0]), "+f"(d[1]), "+f"(d[2]), "+f"(d[3])
                    : "r"(ah[rt][0]), "r"(ah[rt][1]), "r"(ah[rt][2]), "r"(ah[rt][3]),
                      "r"(bh0), "r"(bh1));
                asm volatile(
                    "mma.sync.aligned.m16n8k8.row.col.f32.tf32.tf32.f32 "
                    "{%0,%1,%2,%3}, {%4,%5,%6,%7}, {%8,%9}, {%0,%1,%2,%3};"
                    : "+f"(d[0]), "+f"(d[1]), "+f"(d[2]), "+f"(d[3])
                    : "r"(ah[rt][0]), "r"(ah[rt][1]), "r"(ah[rt][2]), "r"(ah[rt][3]),
                      "r"(bl0), "r"(bl1));
                asm volatile(
                    "mma.sync.aligned.m16n8k8.row.col.f32.tf32.tf32.f32 "
                    "{%0,%1,%2,%3}, {%4,%5,%6,%7}, {%8,%9}, {%0,%1,%2,%3};"
                    : "+f"(d[0]), "+f"(d[1]), "+f"(d[2]), "+f"(d[3])
                    : "r"(al[rt][0]), "r"(al[rt][1]), "r"(al[rt][2]), "r"(al[rt][3]),
                      "r"(bh0), "r"(bh1));
            }
        }

        if (c < 15) {
            int b = 1 - p;
            *(float4*)&Xs[b][xrow][xoff] = xv;
            stageW(b, wv);
            __syncthreads();
            p ^= 1;
        }
    }

#pragma unroll
    for (int rt = 0; rt < 2; rt++) {
        int r0g = row0 + wr * 32 + rt * 16 + g;
        int r1g = r0g + 8;
#pragma unroll
        for (int nt = 0; nt < 8; nt++) {
            int cc = wc * 64 + nt * 8 + 2 * tig;
            if (r0g < N)
                *(__half2*)&Y[(long)r0g * F + cc] = __floats2half2_rn(acc[rt][nt][0], acc[rt][nt][1]);
            if (r1g < N)
                *(__half2*)&Y[(long)r1g * F + cc] = __floats2half2_rn(acc[rt][nt][2], acc[rt][nt][3]);
        }
    }
}

// ---------------- layer 1 gather (CSR, fp16 messages) + fused h@W2 ----------
__device__ __forceinline__ void acc_row(float4& acc, const __half* base, int lane, float n) {
    uint2 u = ((const uint2*)base)[lane];
    float2 f01 = __half22float2(*reinterpret_cast<__half2*>(&u.x));
    float2 f23 = __half22float2(*reinterpret_cast<__half2*>(&u.y));
    acc.x += n * f01.x; acc.y += n * f01.y;
    acc.z += n * f23.x; acc.w += n * f23.y;
}

__global__ void k_gather1(const int* __restrict__ start, const int2* __restrict__ edge,
                          const __half* __restrict__ xwh,
                          const float* __restrict__ dinv, const float* __restrict__ b1,
                          const float* __restrict__ W2,
                          float* __restrict__ emb, float* __restrict__ hw, int N) {
    int node = blockIdx.x * (blockDim.x >> 5) + (threadIdx.x >> 5);
    if (node >= N) return;
    int lane = threadIdx.x & 31;

    float s = dinv[node]; s = s * s;
    float4 acc = make_float4(0.f, 0.f, 0.f, 0.f);
    acc_row(acc, &xwh[(long)node * F], lane, s);

    int e  = start[node];
    int e1 = start[node + 1];
    for (; e + 3 < e1; e += 4) {
        int2 p0 = edge[e],   p1 = edge[e+1], p2 = edge[e+2], p3 = edge[e+3];
        acc_row(acc, &xwh[(long)p0.x * F], lane, __int_as_float(p0.y));
        acc_row(acc, &xwh[(long)p1.x * F], lane, __int_as_float(p1.y));
        acc_row(acc, &xwh[(long)p2.x * F], lane, __int_as_float(p2.y));
        acc_row(acc, &xwh[(long)p3.x * F], lane, __int_as_float(p3.y));
    }
    for (; e < e1; e++) {
        int2 p0 = edge[e];
        acc_row(acc, &xwh[(long)p0.x * F], lane, __int_as_float(p0.y));
    }

    float4 b = ((const float4*)b1)[lane];
    acc.x += b.x; acc.y += b.y; acc.z += b.z; acc.w += b.w;
    acc.x = (acc.x > 0.f) ? acc.x : expm1f(acc.x);
    acc.y = (acc.y > 0.f) ? acc.y : expm1f(acc.y);
    acc.z = (acc.z > 0.f) ? acc.z : expm1f(acc.z);
    acc.w = (acc.w > 0.f) ? acc.w : expm1f(acc.w);
    // streaming store: emb is write-once, keep it out of L2
    __stwt((float4*)&emb[(long)node * F + lane * 4], acc);

    float4 wv = ((const float4*)W2)[lane];
    float d = acc.x * wv.x + acc.y * wv.y + acc.z * wv.z + acc.w * wv.w;
#pragma unroll
    for (int o = 16; o > 0; o >>= 1) d += __shfl_xor_sync(0xFFFFFFFFu, d, o);
    if (lane == 0) hw[node] = d;
}

// ---------------- layer 2 ----------------------------------------------------
__global__ void k_gather2(const int* __restrict__ start, const int2* __restrict__ edge,
                          const float* __restrict__ hw,
                          const float* __restrict__ dinv, const float* __restrict__ b2,
                          float* __restrict__ out, int N) {
    int node = blockIdx.x * blockDim.x + threadIdx.x;
    if (node >= N) return;
    float d = dinv[node];
    float sum = d * d * hw[node];
    int e  = start[node];
    int e1 = start[node + 1];
    for (; e + 1 < e1; e += 2) {
        int2 p0 = edge[e], p1 = edge[e + 1];
        sum += __int_as_float(p0.y) * hw[p0.x] + __int_as_float(p1.y) * hw[p1.x];
    }
    if (e < e1) {
        int2 p0 = edge[e];
        sum += __int_as_float(p0.y) * hw[p0.x];
    }
    float v = sum + b2[0];
    out[node] = 1.0f / (1.0f + expf(-v));
}

// ---------------- launch ------------------------------------------------------
extern "C" void kernel_launch(void* const* d_in, const int* in_sizes, int n_in,
                              void* d_out, int out_size) {
    const float* x   = (const float*)d_in[0];
    const int*   ei  = (const int*)d_in[1];
    const float* ew  = (const float*)d_in[2];
    const float* W1  = (const float*)d_in[3];
    const float* b1  = (const float*)d_in[4];
    const float* W2  = (const float*)d_in[5];
    const float* b2  = (const float*)d_in[6];

    int N = in_sizes[0] / F;
    int E = in_sizes[2];
    const int* row = ei;
    const int* col = ei + E;

    float* out_pred = (float*)d_out;
    float* emb      = (float*)d_out + N;

    unsigned long long* packed = nullptr; cudaGetSymbolAddress((void**)&packed, g_packed);
    float*  dinv  = nullptr; cudaGetSymbolAddress((void**)&dinv,  g_dinv);
    __half* xwh   = nullptr; cudaGetSymbolAddress((void**)&xwh,   g_xwh);
    float*  hw    = nullptr; cudaGetSymbolAddress((void**)&hw,    g_hw);
    int*    start = nullptr; cudaGetSymbolAddress((void**)&start, g_start);
    int*    bsum  = nullptr; cudaGetSymbolAddress((void**)&bsum,  g_bsum);
    int*    rank  = nullptr; cudaGetSymbolAddress((void**)&rank,  g_rank);
    int2*   edge  = nullptr; cudaGetSymbolAddress((void**)&edge,  g_edge);

    int nb = (N + CHUNK - 1) / CHUNK;

    static cudaStream_t s2 = nullptr;
    static cudaEvent_t ev_fork = nullptr, ev_join = nullptr;
    if (s2 == nullptr) {
        cudaStreamCreateWithFlags(&s2, cudaStreamNonBlocking);
        cudaEventCreateWithFlags(&ev_fork, cudaEventDisableTiming);
        cudaEventCreateWithFlags(&ev_join, cudaEventDisableTiming);
    }

    cudaEventRecord(ev_fork, 0);
    cudaStreamWaitEvent(s2, ev_fork, 0);

    // main stream: tf32 tensor-core GEMM (inline W split, fp16 output)
    k_gemm_tf32<<<(N + 127) / 128, 256>>>(x, W1, xwh, N);

    // s2: CSR build (memset init, one packed atomic per edge, atomic-free permute)
    cudaMemsetAsync(packed, 0, (size_t)N * sizeof(unsigned long long), s2);
    k_edge_pass<<<(E + 255) / 256, 256, 0, s2>>>(col, ew, packed, rank, E);
    k_dinv_blocksum<<<nb, 256, 0, s2>>>(packed, dinv, bsum, N);
    k_scan_bsum<<<1, 128, 0, s2>>>(bsum, start, nb, N, E);
    k_scan_scatter<<<nb, 256, 0, s2>>>(packed, bsum, start, N);
    k_permute<<<(E + 255) / 256, 256, 0, s2>>>(row, col, ew, dinv, start, rank, edge, E);

    cudaEventRecord(ev_join, s2);
    cudaStreamWaitEvent(0, ev_join, 0);

    k_gather1<<<(N + 7) / 8, 256>>>(start, edge, xwh, dinv, b1, W2, emb, hw, N);
    k_gather2<<<(N + 255) / 256, 256>>>(start, edge, hw, dinv, b2, out_pred, N);
}